// round 3
// baseline (speedup 1.0000x reference)
#include <cuda_runtime.h>

#define BB 2
#define LL 1024
#define DD 64
#define NROWS (BB*LL)
#define SCALE 0.35355339059327373f

// persistent activations (no allocation allowed)
__device__ float g_qvs[NROWS*DD];
__device__ float g_kvs[NROWS*DD];
__device__ float g_attq[NROWS*DD];
__device__ float g_attk[NROWS*DD];
__device__ float g_q1[NROWS*DD];
__device__ float g_q2[NROWS*DD];
__device__ float g_kk[NROWS*DD];
__device__ float g_vv[NROWS*DD];

// ---------------------------------------------------------------------------
// Embed: row-wise MLP concat(obs,s,f)[7] -> 256 -> 64
// grid 256, 256 thr, 16 rows per CTA; w1/w2 staged in smem once.
// rows 0..2047 = ctx -> kvs, 2048..4095 = test -> qvs
// ---------------------------------------------------------------------------
__global__ __launch_bounds__(256) void embed_kernel(
    const float* __restrict__ s_ctx, const float* __restrict__ f_ctx,
    const float* __restrict__ s_test, const float* __restrict__ table,
    const float* __restrict__ w1, const float* __restrict__ b1,
    const float* __restrict__ w2, const float* __restrict__ b2)
{
    extern __shared__ float sw2[];          // 16384 floats = 64KB
    __shared__ float sw1[7*256];
    __shared__ float xs[8];
    __shared__ float h[256];
    __shared__ float part[256];
    int tid = threadIdx.x;
    for (int n = tid; n < 16384; n += 256) sw2[n] = w2[n];
    for (int n = tid; n < 1792;  n += 256) sw1[n] = w1[n];
    float b1v = b1[tid];
    __syncthreads();

    for (int it = 0; it < 16; ++it) {
        int row = blockIdx.x * 16 + it;
        int sideq = row >> 11;              // 0: ctx, 1: test
        int r = row & 2047;
        int b = r >> 10, pos = r & 1023;
        if (tid < 7) {
            float v;
            if (sideq == 0) {
                v = (tid < 4) ? table[4 + tid]
                  : (tid < 6) ? s_ctx[(b*LL + pos)*2 + tid - 4]
                              : f_ctx[b*LL + pos];
            } else {
                v = (tid < 4) ? table[tid]
                  : (tid < 6) ? s_test[(b*LL + pos)*2 + tid - 4]
                              : 0.f;
            }
            xs[tid] = v;
        }
        __syncthreads();
        float acc = b1v;
#pragma unroll
        for (int i = 0; i < 7; ++i) acc = fmaf(xs[i], sw1[i*256 + tid], acc);
        h[tid] = fmaxf(acc, 0.f);
        __syncthreads();
        int o = tid & 63, half = tid >> 6;
        float p = 0.f;
#pragma unroll 8
        for (int j = half*64; j < half*64 + 64; ++j) p = fmaf(h[j], sw2[j*64 + o], p);
        part[tid] = p;
        __syncthreads();
        if (tid < 64) {
            float v = part[tid] + part[tid+64] + part[tid+128] + part[tid+192] + b2[tid];
            float* dst = sideq ? g_qvs : g_kvs;
            dst[(b*LL + pos)*64 + tid] = v;
        }
        __syncthreads();
    }
}

// ---------------------------------------------------------------------------
// Projections for one block: q1 = qvs@Wq, q2 = kvs@Wq, k = kvs@Wk, v = kvs@Wv
// grid (64, 4), 256 thr; each CTA: 32 rows x 64 cols
// ---------------------------------------------------------------------------
__global__ __launch_bounds__(256) void proj_kernel(
    int iblk,
    const float* __restrict__ wq, const float* __restrict__ bq,
    const float* __restrict__ wk, const float* __restrict__ bk,
    const float* __restrict__ wv, const float* __restrict__ bv)
{
    __shared__ float sW[64*64];
    __shared__ float sX[32*64];
    int tid = threadIdx.x;
    int mat = blockIdx.y;
    const float *X, *W, *bias; float* dst;
    if (mat == 0)      { X = g_qvs; W = wq + iblk*4096; bias = bq + iblk*64; dst = g_q1; }
    else if (mat == 1) { X = g_kvs; W = wq + iblk*4096; bias = bq + iblk*64; dst = g_q2; }
    else if (mat == 2) { X = g_kvs; W = wk + iblk*4096; bias = bk + iblk*64; dst = g_kk; }
    else               { X = g_kvs; W = wv + iblk*4096; bias = bv + iblk*64; dst = g_vv; }
    int row0 = blockIdx.x * 32;
    for (int n = tid; n < 4096; n += 256) sW[n] = W[n];
    for (int n = tid; n < 2048; n += 256) sX[n] = X[row0*64 + n];
    __syncthreads();
    int r = tid >> 3, c0 = (tid & 7) * 8;
    float acc[8];
#pragma unroll
    for (int i = 0; i < 8; ++i) acc[i] = bias[c0 + i];
#pragma unroll 16
    for (int k = 0; k < 64; ++k) {
        float a = sX[r*64 + k];
#pragma unroll
        for (int i = 0; i < 8; ++i) acc[i] = fmaf(a, sW[k*64 + c0 + i], acc[i]);
    }
#pragma unroll
    for (int i = 0; i < 8; ++i) dst[(row0 + r)*64 + c0 + i] = acc[i];
}

// ---------------------------------------------------------------------------
// Fused biased attention + out-proj + residual + LN.
// grid (128, B, 2): z=0 q-side, z=1 k-side. CTA = 8 warps = 8 queries.
// warp-per-query; lanes over keys; branchless softmax (no running max —
// scores are bounded; softmax is shift-invariant); 64-key chunks processed
// as two 32-key halves sharing W2 and Q broadcast loads.
// ---------------------------------------------------------------------------
__global__ __launch_bounds__(256) void attn_kernel(
    int iblk,
    const float* __restrict__ s_test, const float* __restrict__ s_ctx,
    const float* __restrict__ bw1, const float* __restrict__ bb1,
    const float* __restrict__ bw2, const float* __restrict__ bb2,
    const float* __restrict__ wo, const float* __restrict__ bo,
    const float* __restrict__ ns, const float* __restrict__ nb)
{
    __shared__ float4 sKf4[1024];   // 64 keys x 16 float4, XOR swizzled
    __shared__ float4 sVf4[1024];
    __shared__ float  sQ[512];      // 8 queries x 64 (pre-scaled by 1/sqrt(8))
    __shared__ float2 sSk[64];      // 64 key coords
    __shared__ float4 sW2[32];      // dist-bias second layer 16x8

    const int tid = threadIdx.x, wid = tid >> 5, lane = tid & 31;
    const int side = blockIdx.z, b = blockIdx.y;
    const int q = blockIdx.x * 8 + wid;
    const int qrow = b * LL + q;

    const float* Qp  = side ? g_q2 : g_q1;
    const float* sqc = side ? s_ctx : s_test;

    float w1r[16], b1r[16], b2r[8];
    {
        const float* w1g = bw1 + iblk*16;
        const float* b1g = bb1 + iblk*16;
        const float* b2g = bb2 + iblk*8;
#pragma unroll
        for (int j = 0; j < 16; ++j) { w1r[j] = w1g[j]; b1r[j] = b1g[j]; }
#pragma unroll
        for (int h = 0; h < 8; ++h) b2r[h] = b2g[h];
    }
    if (tid < 128) ((float*)sW2)[tid] = bw2[iblk*128 + tid];
    for (int n = tid; n < 512; n += 256)
        sQ[n] = Qp[(b*LL + blockIdx.x*8)*64 + n] * SCALE;
    const float sqx = sqc[qrow*2], sqy = sqc[qrow*2 + 1];

    float l[8], o[64];
#pragma unroll
    for (int h = 0; h < 8; ++h) l[h] = 0.f;
#pragma unroll
    for (int d = 0; d < 64; ++d) o[d] = 0.f;

    const float4* sQf4 = ((const float4*)sQ) + wid*16;
    const int ksw = lane & 15;
    const int kb0 = lane << 4, kb1 = (lane + 32) << 4;

    for (int t = 0; t < 16; ++t) {
        __syncthreads();
        const float4* Kg = (const float4*)(g_kk + (b*LL + t*64)*64);
        const float4* Vg = (const float4*)(g_vv + (b*LL + t*64)*64);
        for (int n = tid; n < 1024; n += 256) {
            int kr = n >> 4, c = n & 15;
            int sw = (kr << 4) + (c ^ (kr & 15));
            sKf4[sw] = Kg[n];
            sVf4[sw] = Vg[n];
        }
        if (tid < 64) sSk[tid] = ((const float2*)s_ctx)[b*LL + t*64 + tid];
        __syncthreads();

        // distances for this lane's two keys
        float2 c0 = sSk[lane], c1 = sSk[lane + 32];
        float dx0 = sqx - c0.x, dy0 = sqy - c0.y;
        float dx1 = sqx - c1.x, dy1 = sqy - c1.y;
        float dist0 = fmaf(dx0, dx0, dy0*dy0);
        float dist1 = fmaf(dx1, dx1, dy1*dy1);

        // scores accumulate into bias[0..7] (key lane), bias[8..15] (key lane+32)
        float bias[16];
#pragma unroll
        for (int h = 0; h < 8; ++h) { bias[h] = b2r[h]; bias[8 + h] = b2r[h]; }

        // distance-bias MLP — W2 broadcasts shared across both keys
#pragma unroll
        for (int j = 0; j < 16; ++j) {
            float h0 = fmaxf(fmaf(dist0, w1r[j], b1r[j]), 0.f);
            float h1 = fmaxf(fmaf(dist1, w1r[j], b1r[j]), 0.f);
            float4 wa = sW2[2*j], wb = sW2[2*j + 1];
            bias[0]  = fmaf(h0, wa.x, bias[0]);
            bias[1]  = fmaf(h0, wa.y, bias[1]);
            bias[2]  = fmaf(h0, wa.z, bias[2]);
            bias[3]  = fmaf(h0, wa.w, bias[3]);
            bias[4]  = fmaf(h0, wb.x, bias[4]);
            bias[5]  = fmaf(h0, wb.y, bias[5]);
            bias[6]  = fmaf(h0, wb.z, bias[6]);
            bias[7]  = fmaf(h0, wb.w, bias[7]);
            bias[8]  = fmaf(h1, wa.x, bias[8]);
            bias[9]  = fmaf(h1, wa.y, bias[9]);
            bias[10] = fmaf(h1, wa.z, bias[10]);
            bias[11] = fmaf(h1, wa.w, bias[11]);
            bias[12] = fmaf(h1, wb.x, bias[12]);
            bias[13] = fmaf(h1, wb.y, bias[13]);
            bias[14] = fmaf(h1, wb.z, bias[14]);
            bias[15] = fmaf(h1, wb.w, bias[15]);
        }

        // QK dots — Q broadcasts shared across both keys (Q pre-scaled)
#pragma unroll
        for (int c = 0; c < 16; ++c) {
            float4 qv  = sQf4[c];
            float4 k0v = sKf4[kb0 + (c ^ ksw)];
            float4 k1v = sKf4[kb1 + (c ^ ksw)];
            int h = c >> 1;
            bias[h]     = fmaf(qv.x, k0v.x, bias[h]);
            bias[h]     = fmaf(qv.y, k0v.y, bias[h]);
            bias[h]     = fmaf(qv.z, k0v.z, bias[h]);
            bias[h]     = fmaf(qv.w, k0v.w, bias[h]);
            bias[8 + h] = fmaf(qv.x, k1v.x, bias[8 + h]);
            bias[8 + h] = fmaf(qv.y, k1v.y, bias[8 + h]);
            bias[8 + h] = fmaf(qv.z, k1v.z, bias[8 + h]);
            bias[8 + h] = fmaf(qv.w, k1v.w, bias[8 + h]);
        }

        // branchless exp + V accumulation
#pragma unroll
        for (int kk = 0; kk < 2; ++kk) {
            const int kb = kk ? kb1 : kb0;
#pragma unroll
            for (int h = 0; h < 8; ++h) {
                float p = __expf(fminf(bias[kk*8 + h], 60.f));
                l[h] += p;
                float4 v0 = sVf4[kb + ((2*h) ^ ksw)];
                float4 v1 = sVf4[kb + ((2*h + 1) ^ ksw)];
                o[h*8+0] = fmaf(p, v0.x, o[h*8+0]);
                o[h*8+1] = fmaf(p, v0.y, o[h*8+1]);
                o[h*8+2] = fmaf(p, v0.z, o[h*8+2]);
                o[h*8+3] = fmaf(p, v0.w, o[h*8+3]);
                o[h*8+4] = fmaf(p, v1.x, o[h*8+4]);
                o[h*8+5] = fmaf(p, v1.y, o[h*8+5]);
                o[h*8+6] = fmaf(p, v1.z, o[h*8+6]);
                o[h*8+7] = fmaf(p, v1.w, o[h*8+7]);
            }
        }
    }

    // lane merge: butterfly sums (no max bookkeeping needed)
#pragma unroll
    for (int h = 0; h < 8; ++h) {
        float lh = l[h];
#pragma unroll
        for (int off = 16; off; off >>= 1)
            lh += __shfl_xor_sync(0xffffffffu, lh, off);
        l[h] = lh;
    }
#pragma unroll
    for (int d = 0; d < 64; ++d) {
        float v = o[d];
#pragma unroll
        for (int off = 16; off; off >>= 1)
            v += __shfl_xor_sync(0xffffffffu, v, off);
        o[d] = v;
    }
#pragma unroll
    for (int h = 0; h < 8; ++h) {
        float inv = 1.f / l[h];
#pragma unroll
        for (int d = 0; d < 8; ++d) o[h*8 + d] *= inv;
    }

    // epilogue: out-proj (Wo reuses sK smem) + residual + LN
    __syncthreads();
    float* sWo = (float*)sKf4;
    const float* Wog = wo + iblk*4096;
    for (int n = tid; n < 4096; n += 256) sWo[n] = Wog[n];
    __syncthreads();

    const int j0 = lane, j1 = lane + 32;
    float acc0 = bo[iblk*64 + j0], acc1 = bo[iblk*64 + j1];
#pragma unroll
    for (int i = 0; i < 64; ++i) {
        float a = o[i];
        acc0 = fmaf(a, sWo[i*64 + j0], acc0);
        acc1 = fmaf(a, sWo[i*64 + j1], acc1);
    }
    const float* src = side ? g_kvs : g_qvs;
    acc0 += src[qrow*64 + j0];
    acc1 += src[qrow*64 + j1];

    float ssum = acc0 + acc1;
#pragma unroll
    for (int off = 16; off; off >>= 1)
        ssum += __shfl_xor_sync(0xffffffffu, ssum, off);
    float mu = ssum * (1.f/64.f);
    float e0 = acc0 - mu, e1 = acc1 - mu;
    float vv = fmaf(e0, e0, e1*e1);
#pragma unroll
    for (int off = 16; off; off >>= 1)
        vv += __shfl_xor_sync(0xffffffffu, vv, off);
    float rstd = rsqrtf(vv * (1.f/64.f) + 1e-6f);

    float* outp = side ? g_attk : g_attq;
    const float* nsp = ns + iblk*64;
    const float* nbp = nb + iblk*64;
    outp[qrow*64 + j0] = e0 * rstd * nsp[j0] + nbp[j0];
    outp[qrow*64 + j1] = e1 * rstd * nsp[j1] + nbp[j1];
}

// ---------------------------------------------------------------------------
// FFN (64->128 relu ->64) + residual + LN.
// grid 256, 256 thr, 16 rows/CTA (2 rows in parallel), weights staged in smem.
// ---------------------------------------------------------------------------
__global__ __launch_bounds__(256) void ffn_kernel(
    int iblk,
    const float* __restrict__ fw1, const float* __restrict__ fb1,
    const float* __restrict__ fw2, const float* __restrict__ fb2,
    const float* __restrict__ ns, const float* __restrict__ nb)
{
    extern __shared__ float dynw[];          // 16384 floats = 64KB
    float* sW1 = dynw;                       // 64x128
    float* sW2 = dynw + 8192;                // 128x64
    __shared__ float sx[2][64], sh[2][128], so[2][64], sred[2][2];

    int tid = threadIdx.x, g = tid >> 7, t = tid & 127;
    for (int n = tid; n < 8192; n += 256) {
        sW1[n] = fw1[iblk*8192 + n];
        sW2[n] = fw2[iblk*8192 + n];
    }
    float b1v = fb1[iblk*128 + t];
    __syncthreads();

    for (int it = 0; it < 8; ++it) {
        int row  = blockIdx.x*16 + it*2 + g;
        int sideR = row >> 11, r = row & 2047;
        const float* src = sideR ? g_attk : g_attq;
        float* dst = sideR ? g_kvs : g_qvs;
        if (t < 64) sx[g][t] = src[r*64 + t];
        __syncthreads();
        float acc = b1v;
#pragma unroll 16
        for (int k = 0; k < 64; ++k) acc = fmaf(sx[g][k], sW1[k*128 + t], acc);
        sh[g][t] = fmaxf(acc, 0.f);
        __syncthreads();
        if (t < 64) {
            float a2 = fb2[iblk*64 + t];
#pragma unroll 16
            for (int k = 0; k < 128; ++k) a2 = fmaf(sh[g][k], sW2[k*64 + t], a2);
            so[g][t] = a2 + sx[g][t];
        }
        __syncthreads();
        if (t < 32) {
            float v0 = so[g][t], v1 = so[g][t + 32];
            float s = v0 + v1;
#pragma unroll
            for (int off = 16; off; off >>= 1)
                s += __shfl_xor_sync(0xffffffffu, s, off);
            float mu = s * (1.f/64.f);
            float e0 = v0 - mu, e1 = v1 - mu;
            float qv = fmaf(e0, e0, e1*e1);
#pragma unroll
            for (int off = 16; off; off >>= 1)
                qv += __shfl_xor_sync(0xffffffffu, qv, off);
            if (t == 0) { sred[g][0] = mu; sred[g][1] = rsqrtf(qv*(1.f/64.f) + 1e-6f); }
        }
        __syncthreads();
        if (t < 64)
            dst[r*64 + t] = (so[g][t] - sred[g][0]) * sred[g][1] * ns[iblk*64 + t]
                          + nb[iblk*64 + t];
        __syncthreads();
    }
}

// ---------------------------------------------------------------------------
// Head: final LN + MLP 64->128 relu ->2, split into (mu, std=exp(lv/2))
// grid 2048, 128 thr.  out = [mu(2048) | std(2048)]
// ---------------------------------------------------------------------------
__global__ __launch_bounds__(128) void head_kernel(
    const float* __restrict__ fns, const float* __restrict__ fnb,
    const float* __restrict__ hw1, const float* __restrict__ hb1,
    const float* __restrict__ hw2, const float* __restrict__ hb2,
    float* __restrict__ out)
{
    __shared__ float sx[64], sh[128], sp0[128], sp1[128], sred[2];
    int row = blockIdx.x, tid = threadIdx.x;
    if (tid < 64) sx[tid] = g_qvs[row*64 + tid];
    __syncthreads();
    if (tid < 32) {
        float v0 = sx[tid], v1 = sx[tid + 32];
        float s = v0 + v1;
#pragma unroll
        for (int off = 16; off; off >>= 1)
            s += __shfl_xor_sync(0xffffffffu, s, off);
        float mu = s * (1.f/64.f);
        float e0 = v0 - mu, e1 = v1 - mu;
        float qv = fmaf(e0, e0, e1*e1);
#pragma unroll
        for (int off = 16; off; off >>= 1)
            qv += __shfl_xor_sync(0xffffffffu, qv, off);
        if (tid == 0) { sred[0] = mu; sred[1] = rsqrtf(qv*(1.f/64.f) + 1e-6f); }
    }
    __syncthreads();
    if (tid < 64) sx[tid] = (sx[tid] - sred[0]) * sred[1] * fns[tid] + fnb[tid];
    __syncthreads();
    float acc = hb1[tid];
#pragma unroll 16
    for (int k = 0; k < 64; ++k) acc = fmaf(sx[k], hw1[k*128 + tid], acc);
    sh[tid] = fmaxf(acc, 0.f);
    __syncthreads();
    sp0[tid] = sh[tid] * hw2[tid*2 + 0];
    sp1[tid] = sh[tid] * hw2[tid*2 + 1];
    __syncthreads();
    for (int s = 64; s > 0; s >>= 1) {
        if (tid < s) { sp0[tid] += sp0[tid + s]; sp1[tid] += sp1[tid + s]; }
        __syncthreads();
    }
    if (tid == 0) {
        out[row]        = sp0[0] + hb2[0];
        out[2048 + row] = __expf(0.5f * (sp1[0] + hb2[1]));
    }
}

// ---------------------------------------------------------------------------
extern "C" void kernel_launch(void* const* d_in, const int* in_sizes, int n_in,
                              void* d_out, int out_size)
{
    const float* s_ctx   = (const float*)d_in[0];
    const float* f_ctx   = (const float*)d_in[1];
    const float* s_test  = (const float*)d_in[2];
    const float* table   = (const float*)d_in[3];
    const float* emb_w1  = (const float*)d_in[4];
    const float* emb_b1  = (const float*)d_in[5];
    const float* emb_w2  = (const float*)d_in[6];
    const float* emb_b2  = (const float*)d_in[7];
    const float* attn_wq = (const float*)d_in[8];
    const float* attn_bq = (const float*)d_in[9];
    const float* attn_wk = (const float*)d_in[10];
    const float* attn_bk = (const float*)d_in[11];
    const float* attn_wv = (const float*)d_in[12];
    const float* attn_bv = (const float*)d_in[13];
    const float* attn_wo = (const float*)d_in[14];
    const float* attn_bo = (const float*)d_in[15];
    const float* ffn_w1  = (const float*)d_in[16];
    const float* ffn_b1  = (const float*)d_in[17];
    const float* ffn_w2  = (const float*)d_in[18];
    const float* ffn_b2  = (const float*)d_in[19];
    const float* bias_w1 = (const float*)d_in[20];
    const float* bias_b1 = (const float*)d_in[21];
    const float* bias_w2 = (const float*)d_in[22];
    const float* bias_b2 = (const float*)d_in[23];
    const float* norm_s  = (const float*)d_in[24];
    const float* norm_b  = (const float*)d_in[25];
    const float* fnorm_s = (const float*)d_in[26];
    const float* fnorm_b = (const float*)d_in[27];
    const float* head_w1 = (const float*)d_in[28];
    const float* head_b1 = (const float*)d_in[29];
    const float* head_w2 = (const float*)d_in[30];
    const float* head_b2 = (const float*)d_in[31];

    static int attr_done = 0;
    if (!attr_done) {
        cudaFuncSetAttribute(embed_kernel,
            cudaFuncAttributeMaxDynamicSharedMemorySize, 65536);
        cudaFuncSetAttribute(ffn_kernel,
            cudaFuncAttributeMaxDynamicSharedMemorySize, 65536);
        attr_done = 1;
    }

    embed_kernel<<<256, 256, 65536>>>(s_ctx, f_ctx, s_test, table,
                                      emb_w1, emb_b1, emb_w2, emb_b2);
    for (int i = 0; i < 6; ++i) {
        proj_kernel<<<dim3(64, 4), 256>>>(i, attn_wq, attn_bq,
                                          attn_wk, attn_bk, attn_wv, attn_bv);
        attn_kernel<<<dim3(128, BB, 2), 256>>>(i, s_test, s_ctx,
                                               bias_w1, bias_b1, bias_w2, bias_b2,
                                               attn_wo, attn_bo, norm_s, norm_b);
        ffn_kernel<<<256, 256, 65536>>>(i, ffn_w1, ffn_b1, ffn_w2, ffn_b2,
                                        norm_s, norm_b);
    }
    head_kernel<<<2048, 128>>>(fnorm_s, fnorm_b, head_w1, head_b1,
                               head_w2, head_b2, (float*)d_out);
}

// round 4
// speedup vs baseline: 1.7087x; 1.7087x over previous
#include <cuda_runtime.h>

#define BB 2
#define LL 1024
#define DD 64
#define NROWS (BB*LL)
#define SCALE 0.35355339059327373f

// persistent activations (no allocation allowed)
__device__ float g_qvs[NROWS*DD];
__device__ float g_kvs[NROWS*DD];
__device__ float g_attq[NROWS*DD];
__device__ float g_attk[NROWS*DD];
__device__ float g_q1[NROWS*DD];
__device__ float g_q2[NROWS*DD];
__device__ float g_kk[NROWS*DD];
__device__ float g_vv[NROWS*DD];

// ---------------------------------------------------------------------------
// Embed: row-wise MLP concat(obs,s,f)[7] -> 256 -> 64   (R2 version)
// grid 4096 (rows 0..2047 = ctx -> kvs, 2048..4095 = test -> qvs), 256 thr
// ---------------------------------------------------------------------------
__global__ __launch_bounds__(256) void embed_kernel(
    const float* __restrict__ s_ctx, const float* __restrict__ f_ctx,
    const float* __restrict__ s_test, const float* __restrict__ table,
    const float* __restrict__ w1, const float* __restrict__ b1,
    const float* __restrict__ w2, const float* __restrict__ b2)
{
    __shared__ float xs[8];
    __shared__ float h[256];
    __shared__ float part[256];
    int row = blockIdx.x, tid = threadIdx.x;
    int sideq = row >> 11;
    int r = row & 2047;
    int b = r >> 10, pos = r & 1023;
    if (tid < 7) {
        float v;
        if (sideq == 0) {
            v = (tid < 4) ? table[4 + tid]
              : (tid < 6) ? s_ctx[(b*LL + pos)*2 + tid - 4]
                          : f_ctx[b*LL + pos];
        } else {
            v = (tid < 4) ? table[tid]
              : (tid < 6) ? s_test[(b*LL + pos)*2 + tid - 4]
                          : 0.f;
        }
        xs[tid] = v;
    }
    __syncthreads();
    float acc = b1[tid];
#pragma unroll
    for (int i = 0; i < 7; ++i) acc = fmaf(xs[i], w1[i*256 + tid], acc);
    h[tid] = fmaxf(acc, 0.f);
    __syncthreads();
    int o = tid & 63, half = tid >> 6;
    float p = 0.f;
#pragma unroll 8
    for (int j = half*64; j < half*64 + 64; ++j) p = fmaf(h[j], w2[j*64 + o], p);
    part[tid] = p;
    __syncthreads();
    if (tid < 64) {
        float v = part[tid] + part[tid+64] + part[tid+128] + part[tid+192] + b2[tid];
        float* dst = sideq ? g_qvs : g_kvs;
        dst[(b*LL + pos)*64 + tid] = v;
    }
}

// ---------------------------------------------------------------------------
// Projections for one block: q1 = qvs@Wq, q2 = kvs@Wq, k = kvs@Wk, v = kvs@Wv
// grid (64, 4), 256 thr; each CTA: 32 rows x 64 cols
// ---------------------------------------------------------------------------
__global__ __launch_bounds__(256) void proj_kernel(
    int iblk,
    const float* __restrict__ wq, const float* __restrict__ bq,
    const float* __restrict__ wk, const float* __restrict__ bk,
    const float* __restrict__ wv, const float* __restrict__ bv)
{
    __shared__ float sW[64*64];
    __shared__ float sX[32*64];
    int tid = threadIdx.x;
    int mat = blockIdx.y;
    const float *X, *W, *bias; float* dst;
    if (mat == 0)      { X = g_qvs; W = wq + iblk*4096; bias = bq + iblk*64; dst = g_q1; }
    else if (mat == 1) { X = g_kvs; W = wq + iblk*4096; bias = bq + iblk*64; dst = g_q2; }
    else if (mat == 2) { X = g_kvs; W = wk + iblk*4096; bias = bk + iblk*64; dst = g_kk; }
    else               { X = g_kvs; W = wv + iblk*4096; bias = bv + iblk*64; dst = g_vv; }
    int row0 = blockIdx.x * 32;
    for (int n = tid; n < 4096; n += 256) sW[n] = W[n];
    for (int n = tid; n < 2048; n += 256) sX[n] = X[row0*64 + n];
    __syncthreads();
    int r = tid >> 3, c0 = (tid & 7) * 8;
    float acc[8];
#pragma unroll
    for (int i = 0; i < 8; ++i) acc[i] = bias[c0 + i];
#pragma unroll 16
    for (int k = 0; k < 64; ++k) {
        float a = sX[r*64 + k];
#pragma unroll
        for (int i = 0; i < 8; ++i) acc[i] = fmaf(a, sW[k*64 + c0 + i], acc[i]);
    }
#pragma unroll
    for (int i = 0; i < 8; ++i) dst[(row0 + r)*64 + c0 + i] = acc[i];
}

// ---------------------------------------------------------------------------
// Fused biased attention + out-proj + residual + LN.
// grid (256, B, 2). CTA = 8 warps = 4 queries; each query owned by a WARP
// PAIR: warp (wid&1)==0 -> heads 0-3, ==1 -> heads 4-7. Lanes parallelize
// keys (2 keys each per 64-key tile). o[32] per thread keeps regs ~<100 so
// 2 CTAs/SM stay resident. Branchless softmax (scores bounded).
// ---------------------------------------------------------------------------
__global__ __launch_bounds__(256, 2) void attn_kernel(
    int iblk,
    const float* __restrict__ s_test, const float* __restrict__ s_ctx,
    const float* __restrict__ bw1, const float* __restrict__ bb1,
    const float* __restrict__ bw2, const float* __restrict__ bb2,
    const float* __restrict__ wo, const float* __restrict__ bo,
    const float* __restrict__ ns, const float* __restrict__ nb)
{
    __shared__ float4 sKf4[1024];   // 64 keys x 16 float4, XOR swizzled
    __shared__ float4 sVf4[1024];
    __shared__ float  sQ[256];      // 4 queries x 64 (pre-scaled by 1/sqrt(8))
    __shared__ float2 sSk[64];      // 64 key coords
    __shared__ float4 sW2[32];      // dist-bias layer2 16x8 (row j = sW2[2j],sW2[2j+1])
    __shared__ float  sW1[16], sB1[16];
    __shared__ float  sO[4*64];     // attn output per query
    __shared__ float  sRed[4][2][2];// per-query per-half {sum, sumsq}

    const int tid = threadIdx.x, wid = tid >> 5, lane = tid & 31;
    const int side = blockIdx.z, b = blockIdx.y;
    const int qc = wid >> 1;            // query within CTA (0..3)
    const int hw = wid & 1;             // head half (0: h0-3, 1: h4-7)
    const int q = blockIdx.x * 4 + qc;
    const int qrow = b * LL + q;

    const float* Qp  = side ? g_q2 : g_q1;
    const float* sqc = side ? s_ctx : s_test;

    if (tid < 128) ((float*)sW2)[tid] = bw2[iblk*128 + tid];
    if (tid < 16)  { sW1[tid] = bw1[iblk*16 + tid]; sB1[tid] = bb1[iblk*16 + tid]; }
    if (tid < 256) sQ[tid] = Qp[(b*LL + blockIdx.x*4)*64 + tid] * SCALE;

    float b2r[4];
#pragma unroll
    for (int h = 0; h < 4; ++h) b2r[h] = bb2[iblk*8 + hw*4 + h];
    const float sqx = sqc[qrow*2], sqy = sqc[qrow*2 + 1];

    float l[4], o[32];
#pragma unroll
    for (int h = 0; h < 4; ++h) l[h] = 0.f;
#pragma unroll
    for (int d = 0; d < 32; ++d) o[d] = 0.f;

    const float4* sQf4 = ((const float4*)sQ) + qc*16;
    const int ksw = lane & 15;                 // same for lane and lane+32
    const int kb0 = lane << 4, kb1 = (lane + 32) << 4;
    const int ho2 = hw * 8;                    // float4 column base for this half

    for (int t = 0; t < 16; ++t) {
        __syncthreads();
        const float4* Kg = (const float4*)(g_kk + (b*LL + t*64)*64);
        const float4* Vg = (const float4*)(g_vv + (b*LL + t*64)*64);
        for (int n = tid; n < 1024; n += 256) {
            int kr = n >> 4, c = n & 15;
            int sw = (kr << 4) + (c ^ (kr & 15));
            sKf4[sw] = Kg[n];
            sVf4[sw] = Vg[n];
        }
        if (tid < 64) sSk[tid] = ((const float2*)s_ctx)[b*LL + t*64 + tid];
        __syncthreads();

        float2 c0 = sSk[lane], c1 = sSk[lane + 32];
        float dx0 = sqx - c0.x, dy0 = sqy - c0.y;
        float dx1 = sqx - c1.x, dy1 = sqy - c1.y;
        float dist0 = fmaf(dx0, dx0, dy0*dy0);
        float dist1 = fmaf(dx1, dx1, dy1*dy1);

        // bias[0..3]: key=lane, heads hw*4.. ; bias[4..7]: key=lane+32
        float bias[8];
#pragma unroll
        for (int h = 0; h < 4; ++h) { bias[h] = b2r[h]; bias[4 + h] = b2r[h]; }

#pragma unroll
        for (int j = 0; j < 16; ++j) {
            float w1v = sW1[j], b1v = sB1[j];
            float h0 = fmaxf(fmaf(dist0, w1v, b1v), 0.f);
            float h1 = fmaxf(fmaf(dist1, w1v, b1v), 0.f);
            float4 wv = sW2[2*j + hw];
            bias[0] = fmaf(h0, wv.x, bias[0]);
            bias[1] = fmaf(h0, wv.y, bias[1]);
            bias[2] = fmaf(h0, wv.z, bias[2]);
            bias[3] = fmaf(h0, wv.w, bias[3]);
            bias[4] = fmaf(h1, wv.x, bias[4]);
            bias[5] = fmaf(h1, wv.y, bias[5]);
            bias[6] = fmaf(h1, wv.z, bias[6]);
            bias[7] = fmaf(h1, wv.w, bias[7]);
        }

        // QK dots for this half's 4 heads (8 float4 columns)
#pragma unroll
        for (int cc = 0; cc < 8; ++cc) {
            int c = ho2 + cc;
            float4 qv  = sQf4[c];
            float4 k0v = sKf4[kb0 + (c ^ ksw)];
            float4 k1v = sKf4[kb1 + (c ^ ksw)];
            int h = cc >> 1;
            bias[h]     = fmaf(qv.x, k0v.x, bias[h]);
            bias[h]     = fmaf(qv.y, k0v.y, bias[h]);
            bias[h]     = fmaf(qv.z, k0v.z, bias[h]);
            bias[h]     = fmaf(qv.w, k0v.w, bias[h]);
            bias[4 + h] = fmaf(qv.x, k1v.x, bias[4 + h]);
            bias[4 + h] = fmaf(qv.y, k1v.y, bias[4 + h]);
            bias[4 + h] = fmaf(qv.z, k1v.z, bias[4 + h]);
            bias[4 + h] = fmaf(qv.w, k1v.w, bias[4 + h]);
        }

        // branchless exp + V accumulation
#pragma unroll
        for (int kk = 0; kk < 2; ++kk) {
            const int kb = kk ? kb1 : kb0;
#pragma unroll
            for (int h = 0; h < 4; ++h) {
                float p = __expf(fminf(bias[kk*4 + h], 60.f));
                l[h] += p;
                int hc = ho2 + 2*h;
                float4 v0 = sVf4[kb + (hc ^ ksw)];
                float4 v1 = sVf4[kb + ((hc + 1) ^ ksw)];
                o[h*8+0] = fmaf(p, v0.x, o[h*8+0]);
                o[h*8+1] = fmaf(p, v0.y, o[h*8+1]);
                o[h*8+2] = fmaf(p, v0.z, o[h*8+2]);
                o[h*8+3] = fmaf(p, v0.w, o[h*8+3]);
                o[h*8+4] = fmaf(p, v1.x, o[h*8+4]);
                o[h*8+5] = fmaf(p, v1.y, o[h*8+5]);
                o[h*8+6] = fmaf(p, v1.z, o[h*8+6]);
                o[h*8+7] = fmaf(p, v1.w, o[h*8+7]);
            }
        }
    }

    // merge lanes (butterfly): l and o
#pragma unroll
    for (int h = 0; h < 4; ++h) {
        float lh = l[h];
#pragma unroll
        for (int off = 16; off; off >>= 1)
            lh += __shfl_xor_sync(0xffffffffu, lh, off);
        l[h] = lh;
    }
#pragma unroll
    for (int d = 0; d < 32; ++d) {
        float v = o[d];
#pragma unroll
        for (int off = 16; off; off >>= 1)
            v += __shfl_xor_sync(0xffffffffu, v, off);
        o[d] = v;
    }
#pragma unroll
    for (int h = 0; h < 4; ++h) {
        float inv = 1.f / l[h];
#pragma unroll
        for (int d = 0; d < 8; ++d) o[h*8 + d] *= inv;
    }
    // lane i should hold o[i] for the smem write (static-index selection)
    float myv = 0.f;
#pragma unroll
    for (int i = 0; i < 32; ++i)
        if (lane == i) myv = o[i];

    __syncthreads();                 // all warps done reading sK/sV
    sO[qc*64 + hw*32 + lane] = myv;  // note: half hw covers cols hw*32..hw*32+31
    // stage Wo into sK region
    float* sWo = (float*)sKf4;
    const float* Wog = wo + iblk*4096;
    for (int n = tid; n < 4096; n += 256) sWo[n] = Wog[n];
    __syncthreads();

    // out-proj: warp pair computes 64 columns; this warp: col = hw*32 + lane
    const int col = hw*32 + lane;
    float acc = bo[iblk*64 + col];
#pragma unroll 16
    for (int i = 0; i < 64; ++i)
        acc = fmaf(sO[qc*64 + i], sWo[i*64 + col], acc);
    const float* src = side ? g_kvs : g_qvs;
    acc += src[qrow*64 + col];

    // LN across the 64 columns of this query (spread over 2 warps)
    float s1 = acc, s2 = acc*acc;
#pragma unroll
    for (int off = 16; off; off >>= 1) {
        s1 += __shfl_xor_sync(0xffffffffu, s1, off);
        s2 += __shfl_xor_sync(0xffffffffu, s2, off);
    }
    if (lane == 0) { sRed[qc][hw][0] = s1; sRed[qc][hw][1] = s2; }
    __syncthreads();
    float tot  = sRed[qc][0][0] + sRed[qc][1][0];
    float tot2 = sRed[qc][0][1] + sRed[qc][1][1];
    float mu = tot * (1.f/64.f);
    float var = tot2 * (1.f/64.f) - mu*mu;
    float rstd = rsqrtf(var + 1e-6f);

    float* outp = side ? g_attk : g_attq;
    outp[qrow*64 + col] = (acc - mu) * rstd * ns[iblk*64 + col] + nb[iblk*64 + col];
}

// ---------------------------------------------------------------------------
// FFN (64->128 relu ->64) + residual + LN.  (R2 version)
// grid 4096 (q rows then k rows), 128 thr
// ---------------------------------------------------------------------------
__global__ __launch_bounds__(128) void ffn_kernel(
    int iblk,
    const float* __restrict__ fw1, const float* __restrict__ fb1,
    const float* __restrict__ fw2, const float* __restrict__ fb2,
    const float* __restrict__ ns, const float* __restrict__ nb)
{
    __shared__ float sx[64], sh[128], so[64], sred[2];
    int row = blockIdx.x, tid = threadIdx.x;
    int side = row >> 11, r = row & 2047;
    const float* src = side ? g_attk : g_attq;
    float* dst = side ? g_kvs : g_qvs;
    if (tid < 64) sx[tid] = src[r*64 + tid];
    __syncthreads();
    const float* W1 = fw1 + iblk*64*128;
    float acc = fb1[iblk*128 + tid];
#pragma unroll 16
    for (int k = 0; k < 64; ++k) acc = fmaf(sx[k], W1[k*128 + tid], acc);
    sh[tid] = fmaxf(acc, 0.f);
    __syncthreads();
    if (tid < 64) {
        const float* W2 = fw2 + iblk*128*64;
        float a2 = fb2[iblk*64 + tid];
#pragma unroll 16
        for (int k = 0; k < 128; ++k) a2 = fmaf(sh[k], W2[k*64 + tid], a2);
        so[tid] = a2 + sx[tid];
    }
    __syncthreads();
    if (tid < 32) {
        float v0 = so[tid], v1 = so[tid + 32];
        float s = v0 + v1;
#pragma unroll
        for (int off = 16; off; off >>= 1)
            s += __shfl_xor_sync(0xffffffffu, s, off);
        float mu = s * (1.f/64.f);
        float e0 = v0 - mu, e1 = v1 - mu;
        float qv = fmaf(e0, e0, e1*e1);
#pragma unroll
        for (int off = 16; off; off >>= 1)
            qv += __shfl_xor_sync(0xffffffffu, qv, off);
        if (tid == 0) { sred[0] = mu; sred[1] = rsqrtf(qv*(1.f/64.f) + 1e-6f); }
    }
    __syncthreads();
    if (tid < 64)
        dst[r*64 + tid] = (so[tid] - sred[0]) * sred[1] * ns[iblk*64 + tid] + nb[iblk*64 + tid];
}

// ---------------------------------------------------------------------------
// Head: final LN + MLP 64->128 relu ->2, split into (mu, std=exp(lv/2))
// grid 2048, 128 thr.  out = [mu(2048) | std(2048)]
// ---------------------------------------------------------------------------
__global__ __launch_bounds__(128) void head_kernel(
    const float* __restrict__ fns, const float* __restrict__ fnb,
    const float* __restrict__ hw1, const float* __restrict__ hb1,
    const float* __restrict__ hw2, const float* __restrict__ hb2,
    float* __restrict__ out)
{
    __shared__ float sx[64], sh[128], sp0[128], sp1[128], sred[2];
    int row = blockIdx.x, tid = threadIdx.x;
    if (tid < 64) sx[tid] = g_qvs[row*64 + tid];
    __syncthreads();
    if (tid < 32) {
        float v0 = sx[tid], v1 = sx[tid + 32];
        float s = v0 + v1;
#pragma unroll
        for (int off = 16; off; off >>= 1)
            s += __shfl_xor_sync(0xffffffffu, s, off);
        float mu = s * (1.f/64.f);
        float e0 = v0 - mu, e1 = v1 - mu;
        float qv = fmaf(e0, e0, e1*e1);
#pragma unroll
        for (int off = 16; off; off >>= 1)
            qv += __shfl_xor_sync(0xffffffffu, qv, off);
        if (tid == 0) { sred[0] = mu; sred[1] = rsqrtf(qv*(1.f/64.f) + 1e-6f); }
    }
    __syncthreads();
    if (tid < 64) sx[tid] = (sx[tid] - sred[0]) * sred[1] * fns[tid] + fnb[tid];
    __syncthreads();
    float acc = hb1[tid];
#pragma unroll 16
    for (int k = 0; k < 64; ++k) acc = fmaf(sx[k], hw1[k*128 + tid], acc);
    sh[tid] = fmaxf(acc, 0.f);
    __syncthreads();
    sp0[tid] = sh[tid] * hw2[tid*2 + 0];
    sp1[tid] = sh[tid] * hw2[tid*2 + 1];
    __syncthreads();
    for (int s = 64; s > 0; s >>= 1) {
        if (tid < s) { sp0[tid] += sp0[tid + s]; sp1[tid] += sp1[tid + s]; }
        __syncthreads();
    }
    if (tid == 0) {
        out[row]        = sp0[0] + hb2[0];
        out[2048 + row] = __expf(0.5f * (sp1[0] + hb2[1]));
    }
}

// ---------------------------------------------------------------------------
extern "C" void kernel_launch(void* const* d_in, const int* in_sizes, int n_in,
                              void* d_out, int out_size)
{
    const float* s_ctx   = (const float*)d_in[0];
    const float* f_ctx   = (const float*)d_in[1];
    const float* s_test  = (const float*)d_in[2];
    const float* table   = (const float*)d_in[3];
    const float* emb_w1  = (const float*)d_in[4];
    const float* emb_b1  = (const float*)d_in[5];
    const float* emb_w2  = (const float*)d_in[6];
    const float* emb_b2  = (const float*)d_in[7];
    const float* attn_wq = (const float*)d_in[8];
    const float* attn_bq = (const float*)d_in[9];
    const float* attn_wk = (const float*)d_in[10];
    const float* attn_bk = (const float*)d_in[11];
    const float* attn_wv = (const float*)d_in[12];
    const float* attn_bv = (const float*)d_in[13];
    const float* attn_wo = (const float*)d_in[14];
    const float* attn_bo = (const float*)d_in[15];
    const float* ffn_w1  = (const float*)d_in[16];
    const float* ffn_b1  = (const float*)d_in[17];
    const float* ffn_w2  = (const float*)d_in[18];
    const float* ffn_b2  = (const float*)d_in[19];
    const float* bias_w1 = (const float*)d_in[20];
    const float* bias_b1 = (const float*)d_in[21];
    const float* bias_w2 = (const float*)d_in[22];
    const float* bias_b2 = (const float*)d_in[23];
    const float* norm_s  = (const float*)d_in[24];
    const float* norm_b  = (const float*)d_in[25];
    const float* fnorm_s = (const float*)d_in[26];
    const float* fnorm_b = (const float*)d_in[27];
    const float* head_w1 = (const float*)d_in[28];
    const float* head_b1 = (const float*)d_in[29];
    const float* head_w2 = (const float*)d_in[30];
    const float* head_b2 = (const float*)d_in[31];

    embed_kernel<<<4096, 256>>>(s_ctx, f_ctx, s_test, table,
                                emb_w1, emb_b1, emb_w2, emb_b2);
    for (int i = 0; i < 6; ++i) {
        proj_kernel<<<dim3(64, 4), 256>>>(i, attn_wq, attn_bq,
                                          attn_wk, attn_bk, attn_wv, attn_bv);
        attn_kernel<<<dim3(256, BB, 2), 256>>>(i, s_test, s_ctx,
                                               bias_w1, bias_b1, bias_w2, bias_b2,
                                               attn_wo, attn_bo, norm_s, norm_b);
        ffn_kernel<<<4096, 128>>>(i, ffn_w1, ffn_b1, ffn_w2, ffn_b2,
                                  norm_s, norm_b);
    }
    head_kernel<<<2048, 128>>>(fnorm_s, fnorm_b, head_w1, head_b1,
                               head_w2, head_b2, (float*)d_out);
}

// round 6
// speedup vs baseline: 2.0303x; 1.1882x over previous
#include <cuda_runtime.h>

#define BB 2
#define LL 1024
#define DD 64
#define NROWS (BB*LL)
#define SCALE 0.35355339059327373f

// persistent activations (no allocation allowed)
__device__ float g_qvs[NROWS*DD];
__device__ float g_kvs[NROWS*DD];
__device__ float g_attq[NROWS*DD];
__device__ float g_attk[NROWS*DD];
__device__ float g_q1[NROWS*DD];
__device__ float g_q2[NROWS*DD];
__device__ float g_kk[NROWS*DD];
__device__ float g_vv[NROWS*DD];

// piecewise-linear distance-bias tables (per block)
__device__ float g_pl_t[6][16];       // sorted breakpoints
__device__ float g_pl_AC[6][17][16];  // per interval: A[8], C[8] (C includes b2)

// ---------------------------------------------------------------------------
// Setup: fold dist-bias MLP (1->16 relu ->8) into 17-interval piecewise-linear
// form. bias_h(d) = A_h(m)*d + C_h(m), m = #{t_i < d}. Exact up to fp reassoc.
// ---------------------------------------------------------------------------
__global__ void bias_setup_kernel(
    const float* __restrict__ bw1, const float* __restrict__ bb1,
    const float* __restrict__ bw2, const float* __restrict__ bb2)
{
    int i = blockIdx.x;
    if (threadIdx.x != 0) return;
    float w1[16], b1[16], t[16];
    for (int j = 0; j < 16; ++j) {
        w1[j] = bw1[i*16 + j];
        b1[j] = bb1[i*16 + j];
        t[j]  = (w1[j] != 0.f) ? (-b1[j] / w1[j]) : -1e30f;
    }
    int ord[16];
    for (int j = 0; j < 16; ++j) ord[j] = j;
    for (int a = 1; a < 16; ++a) {          // insertion sort by t
        int o = ord[a]; float tv = t[o]; int b = a - 1;
        while (b >= 0 && t[ord[b]] > tv) { ord[b+1] = ord[b]; --b; }
        ord[b+1] = o;
    }
    for (int j = 0; j < 16; ++j) g_pl_t[i][j] = t[ord[j]];
    for (int m = 0; m <= 16; ++m) {
        float A[8], C[8];
        for (int h = 0; h < 8; ++h) { A[h] = 0.f; C[h] = 0.f; }
        for (int a = 0; a < 16; ++a) {
            int j = ord[a];
            bool act;
            if (w1[j] > 0.f)      act = (a < m);    // active for d > t_j
            else if (w1[j] < 0.f) act = (a >= m);   // active for d < t_j
            else                  act = (b1[j] > 0.f);
            if (act) {
                for (int h = 0; h < 8; ++h) {
                    A[h] += w1[j] * bw2[i*128 + j*8 + h];
                    C[h] += b1[j] * bw2[i*128 + j*8 + h];
                }
            }
        }
        for (int h = 0; h < 8; ++h) {
            g_pl_AC[i][m][h]     = A[h];
            g_pl_AC[i][m][8 + h] = C[h] + bb2[i*8 + h];
        }
    }
}

// ---------------------------------------------------------------------------
// Embed: row-wise MLP concat(obs,s,f)[7] -> 256 -> 64
// grid 4096 (rows 0..2047 = ctx -> kvs, 2048..4095 = test -> qvs), 256 thr
// ---------------------------------------------------------------------------
__global__ __launch_bounds__(256) void embed_kernel(
    const float* __restrict__ s_ctx, const float* __restrict__ f_ctx,
    const float* __restrict__ s_test, const float* __restrict__ table,
    const float* __restrict__ w1, const float* __restrict__ b1,
    const float* __restrict__ w2, const float* __restrict__ b2)
{
    __shared__ float xs[8];
    __shared__ float h[256];
    __shared__ float part[256];
    int row = blockIdx.x, tid = threadIdx.x;
    int sideq = row >> 11;
    int r = row & 2047;
    int b = r >> 10, pos = r & 1023;
    if (tid < 7) {
        float v;
        if (sideq == 0) {
            v = (tid < 4) ? table[4 + tid]
              : (tid < 6) ? s_ctx[(b*LL + pos)*2 + tid - 4]
                          : f_ctx[b*LL + pos];
        } else {
            v = (tid < 4) ? table[tid]
              : (tid < 6) ? s_test[(b*LL + pos)*2 + tid - 4]
                          : 0.f;
        }
        xs[tid] = v;
    }
    __syncthreads();
    float acc = b1[tid];
#pragma unroll
    for (int i = 0; i < 7; ++i) acc = fmaf(xs[i], w1[i*256 + tid], acc);
    h[tid] = fmaxf(acc, 0.f);
    __syncthreads();
    int o = tid & 63, half = tid >> 6;
    float p = 0.f;
#pragma unroll 8
    for (int j = half*64; j < half*64 + 64; ++j) p = fmaf(h[j], w2[j*64 + o], p);
    part[tid] = p;
    __syncthreads();
    if (tid < 64) {
        float v = part[tid] + part[tid+64] + part[tid+128] + part[tid+192] + b2[tid];
        float* dst = sideq ? g_qvs : g_kvs;
        dst[(b*LL + pos)*64 + tid] = v;
    }
}

// ---------------------------------------------------------------------------
// Projections (block 0 only): q1=qvs@Wq, q2=kvs@Wq, kk=kvs@Wk, vv=kvs@Wv
// grid (64, 4), 256 thr
// ---------------------------------------------------------------------------
__global__ __launch_bounds__(256) void proj_kernel(
    int iblk,
    const float* __restrict__ wq, const float* __restrict__ bq,
    const float* __restrict__ wk, const float* __restrict__ bk,
    const float* __restrict__ wv, const float* __restrict__ bv)
{
    __shared__ float sW[64*64];
    __shared__ float sX[32*64];
    int tid = threadIdx.x;
    int mat = blockIdx.y;
    const float *X, *W, *bias; float* dst;
    if (mat == 0)      { X = g_qvs; W = wq + iblk*4096; bias = bq + iblk*64; dst = g_q1; }
    else if (mat == 1) { X = g_kvs; W = wq + iblk*4096; bias = bq + iblk*64; dst = g_q2; }
    else if (mat == 2) { X = g_kvs; W = wk + iblk*4096; bias = bk + iblk*64; dst = g_kk; }
    else               { X = g_kvs; W = wv + iblk*4096; bias = bv + iblk*64; dst = g_vv; }
    int row0 = blockIdx.x * 32;
    for (int n = tid; n < 4096; n += 256) sW[n] = W[n];
    for (int n = tid; n < 2048; n += 256) sX[n] = X[row0*64 + n];
    __syncthreads();
    int r = tid >> 3, c0 = (tid & 7) * 8;
    float acc[8];
#pragma unroll
    for (int i = 0; i < 8; ++i) acc[i] = bias[c0 + i];
#pragma unroll 16
    for (int k = 0; k < 64; ++k) {
        float a = sX[r*64 + k];
#pragma unroll
        for (int i = 0; i < 8; ++i) acc[i] = fmaf(a, sW[k*64 + c0 + i], acc[i]);
    }
#pragma unroll
    for (int i = 0; i < 8; ++i) dst[(row0 + r)*64 + c0 + i] = acc[i];
}

// ---------------------------------------------------------------------------
// Fused biased attention + out-proj + residual + LN.
// grid (256, B, 2). CTA = 8 warps = 4 queries; warp pair per query
// (heads 0-3 / 4-7). Piecewise-linear bias: m = #{t_i < d}, then
// bias_h = fma(A_h[m], d, C_h[m]). Branchless softmax.
// ---------------------------------------------------------------------------
__global__ __launch_bounds__(256, 2) void attn_kernel(
    int iblk,
    const float* __restrict__ s_test, const float* __restrict__ s_ctx,
    const float* __restrict__ wo, const float* __restrict__ bo,
    const float* __restrict__ ns, const float* __restrict__ nb)
{
    __shared__ float4 sKf4[1024];   // 64 keys x 16 float4, XOR swizzled
    __shared__ float4 sVf4[1024];
    __shared__ float  sQ[256];      // 4 queries x 64 (pre-scaled)
    __shared__ float2 sSk[64];
    __shared__ float4 sAC4[68];     // 17 intervals x {A0-3,A4-7,C0-3,C4-7}
    __shared__ float  sO[4*64];
    __shared__ float  sRed[4][2][2];

    const int tid = threadIdx.x, wid = tid >> 5, lane = tid & 31;
    const int side = blockIdx.z, b = blockIdx.y;
    const int qc = wid >> 1;
    const int hw = wid & 1;
    const int q = blockIdx.x * 4 + qc;
    const int qrow = b * LL + q;

    const float* Qp  = side ? g_q2 : g_q1;
    const float* sqc = side ? s_ctx : s_test;

    // FIX (R5 bug): stage all 272 floats with a strided loop — 256 threads
    // previously left interval m=16 (indices 256..271) uninitialized.
    for (int n = tid; n < 272; n += 256)
        ((float*)sAC4)[n] = ((const float*)g_pl_AC)[iblk*272 + n];
    if (tid < 256) sQ[tid] = Qp[(b*LL + blockIdx.x*4)*64 + tid] * SCALE;

    float tr[16];
#pragma unroll
    for (int i = 0; i < 16; ++i) tr[i] = g_pl_t[iblk][i];
    const float sqx = sqc[qrow*2], sqy = sqc[qrow*2 + 1];

    float l[4], o[32];
#pragma unroll
    for (int h = 0; h < 4; ++h) l[h] = 0.f;
#pragma unroll
    for (int d = 0; d < 32; ++d) o[d] = 0.f;

    const float4* sQf4 = ((const float4*)sQ) + qc*16;
    const int ksw = lane & 15;
    const int kb0 = lane << 4, kb1 = (lane + 32) << 4;
    const int ho2 = hw * 8;

    for (int t = 0; t < 16; ++t) {
        __syncthreads();
        const float4* Kg = (const float4*)(g_kk + (b*LL + t*64)*64);
        const float4* Vg = (const float4*)(g_vv + (b*LL + t*64)*64);
        for (int n = tid; n < 1024; n += 256) {
            int kr = n >> 4, c = n & 15;
            int sw = (kr << 4) + (c ^ (kr & 15));
            sKf4[sw] = Kg[n];
            sVf4[sw] = Vg[n];
        }
        if (tid < 64) sSk[tid] = ((const float2*)s_ctx)[b*LL + t*64 + tid];
        __syncthreads();

        float2 c0 = sSk[lane], c1 = sSk[lane + 32];
        float dx0 = sqx - c0.x, dy0 = sqy - c0.y;
        float dx1 = sqx - c1.x, dy1 = sqy - c1.y;
        float dist0 = fmaf(dx0, dx0, dy0*dy0);
        float dist1 = fmaf(dx1, dx1, dy1*dy1);

        // interval search (piecewise-linear bias)
        int m0 = 0, m1 = 0;
#pragma unroll
        for (int i = 0; i < 16; ++i) {
            m0 += (dist0 > tr[i]) ? 1 : 0;
            m1 += (dist1 > tr[i]) ? 1 : 0;
        }
        float4 A0 = sAC4[m0*4 + hw],     A1 = sAC4[m1*4 + hw];
        float4 C0 = sAC4[m0*4 + 2 + hw], C1 = sAC4[m1*4 + 2 + hw];

        float bias[8];
        bias[0] = fmaf(A0.x, dist0, C0.x);
        bias[1] = fmaf(A0.y, dist0, C0.y);
        bias[2] = fmaf(A0.z, dist0, C0.z);
        bias[3] = fmaf(A0.w, dist0, C0.w);
        bias[4] = fmaf(A1.x, dist1, C1.x);
        bias[5] = fmaf(A1.y, dist1, C1.y);
        bias[6] = fmaf(A1.z, dist1, C1.z);
        bias[7] = fmaf(A1.w, dist1, C1.w);

        // QK dots for this half's 4 heads (Q pre-scaled)
#pragma unroll
        for (int cc = 0; cc < 8; ++cc) {
            int c = ho2 + cc;
            float4 qv  = sQf4[c];
            float4 k0v = sKf4[kb0 + (c ^ ksw)];
            float4 k1v = sKf4[kb1 + (c ^ ksw)];
            int h = cc >> 1;
            bias[h]     = fmaf(qv.x, k0v.x, bias[h]);
            bias[h]     = fmaf(qv.y, k0v.y, bias[h]);
            bias[h]     = fmaf(qv.z, k0v.z, bias[h]);
            bias[h]     = fmaf(qv.w, k0v.w, bias[h]);
            bias[4 + h] = fmaf(qv.x, k1v.x, bias[4 + h]);
            bias[4 + h] = fmaf(qv.y, k1v.y, bias[4 + h]);
            bias[4 + h] = fmaf(qv.z, k1v.z, bias[4 + h]);
            bias[4 + h] = fmaf(qv.w, k1v.w, bias[4 + h]);
        }

        // branchless exp + V accumulation
#pragma unroll
        for (int kk = 0; kk < 2; ++kk) {
            const int kb = kk ? kb1 : kb0;
#pragma unroll
            for (int h = 0; h < 4; ++h) {
                float p = __expf(fminf(bias[kk*4 + h], 60.f));
                l[h] += p;
                int hc = ho2 + 2*h;
                float4 v0 = sVf4[kb + (hc ^ ksw)];
                float4 v1 = sVf4[kb + ((hc + 1) ^ ksw)];
                o[h*8+0] = fmaf(p, v0.x, o[h*8+0]);
                o[h*8+1] = fmaf(p, v0.y, o[h*8+1]);
                o[h*8+2] = fmaf(p, v0.z, o[h*8+2]);
                o[h*8+3] = fmaf(p, v0.w, o[h*8+3]);
                o[h*8+4] = fmaf(p, v1.x, o[h*8+4]);
                o[h*8+5] = fmaf(p, v1.y, o[h*8+5]);
                o[h*8+6] = fmaf(p, v1.z, o[h*8+6]);
                o[h*8+7] = fmaf(p, v1.w, o[h*8+7]);
            }
        }
    }

    // merge lanes (butterfly)
#pragma unroll
    for (int h = 0; h < 4; ++h) {
        float lh = l[h];
#pragma unroll
        for (int off = 16; off; off >>= 1)
            lh += __shfl_xor_sync(0xffffffffu, lh, off);
        l[h] = lh;
    }
#pragma unroll
    for (int d = 0; d < 32; ++d) {
        float v = o[d];
#pragma unroll
        for (int off = 16; off; off >>= 1)
            v += __shfl_xor_sync(0xffffffffu, v, off);
        o[d] = v;
    }
#pragma unroll
    for (int h = 0; h < 4; ++h) {
        float inv = 1.f / l[h];
#pragma unroll
        for (int d = 0; d < 8; ++d) o[h*8 + d] *= inv;
    }
    float myv = 0.f;
#pragma unroll
    for (int i = 0; i < 32; ++i)
        if (lane == i) myv = o[i];

    __syncthreads();
    sO[qc*64 + hw*32 + lane] = myv;
    float* sWo = (float*)sKf4;
    const float* Wog = wo + iblk*4096;
    for (int n = tid; n < 4096; n += 256) sWo[n] = Wog[n];
    __syncthreads();

    const int col = hw*32 + lane;
    float acc = bo[iblk*64 + col];
#pragma unroll 16
    for (int i = 0; i < 64; ++i)
        acc = fmaf(sO[qc*64 + i], sWo[i*64 + col], acc);
    const float* src = side ? g_kvs : g_qvs;
    acc += src[qrow*64 + col];

    float s1 = acc, s2 = acc*acc;
#pragma unroll
    for (int off = 16; off; off >>= 1) {
        s1 += __shfl_xor_sync(0xffffffffu, s1, off);
        s2 += __shfl_xor_sync(0xffffffffu, s2, off);
    }
    if (lane == 0) { sRed[qc][hw][0] = s1; sRed[qc][hw][1] = s2; }
    __syncthreads();
    float tot  = sRed[qc][0][0] + sRed[qc][1][0];
    float tot2 = sRed[qc][0][1] + sRed[qc][1][1];
    float mu = tot * (1.f/64.f);
    float var = tot2 * (1.f/64.f) - mu*mu;
    float rstd = rsqrtf(var + 1e-6f);

    float* outp = side ? g_attk : g_attq;
    outp[qrow*64 + col] = (acc - mu) * rstd * ns[iblk*64 + col] + nb[iblk*64 + col];
}

// ---------------------------------------------------------------------------
// FFN (64->128 relu ->64) + residual + LN + NEXT-BLOCK projections.
// grid 512, 128 thr, 8 rows/CTA. Weight loads from L2 reused across 8 rows
// (ILP hides latency; no giant smem staging).
// ---------------------------------------------------------------------------
__global__ __launch_bounds__(128) void ffnproj_kernel(
    int iblk, int nblk,   // nblk = next block for proj, or -1
    const float* __restrict__ fw1, const float* __restrict__ fb1,
    const float* __restrict__ fw2, const float* __restrict__ fb2,
    const float* __restrict__ ns, const float* __restrict__ nb,
    const float* __restrict__ wq, const float* __restrict__ bq,
    const float* __restrict__ wk, const float* __restrict__ bk,
    const float* __restrict__ wv, const float* __restrict__ bv)
{
    __shared__ float sx[8][64];
    __shared__ float sh[8][128];
    __shared__ float sy[8][64];
    __shared__ float sred[8][2][2];

    int tid = threadIdx.x;
    int row0 = blockIdx.x * 8;
    int side = row0 >> 11;
    int r0 = row0 & 2047;
    const float* src = side ? g_attk : g_attq;
    float* dst = side ? g_kvs : g_qvs;

    for (int n = tid; n < 512; n += 128) sx[n >> 6][n & 63] = src[r0*64 + n];
    __syncthreads();

    // layer 1: thread t owns hidden unit t for all 8 rows
    const float* W1 = fw1 + iblk*8192;
    float b1v = fb1[iblk*128 + tid];
    float acc[8];
#pragma unroll
    for (int r = 0; r < 8; ++r) acc[r] = b1v;
#pragma unroll 8
    for (int k = 0; k < 64; ++k) {
        float w = W1[k*128 + tid];
#pragma unroll
        for (int r = 0; r < 8; ++r) acc[r] = fmaf(sx[r][k], w, acc[r]);
    }
#pragma unroll
    for (int r = 0; r < 8; ++r) sh[r][tid] = fmaxf(acc[r], 0.f);
    __syncthreads();

    // layer 2 + residual: col c = tid&63, rows g*4..g*4+3
    const float* W2 = fw2 + iblk*8192;
    int c = tid & 63, g = tid >> 6;
    float b2v = fb2[iblk*64 + c];
    float a2[4];
#pragma unroll
    for (int r = 0; r < 4; ++r) a2[r] = b2v;
#pragma unroll 8
    for (int k = 0; k < 128; ++k) {
        float w = W2[k*64 + c];
#pragma unroll
        for (int r = 0; r < 4; ++r) a2[r] = fmaf(sh[g*4 + r][k], w, a2[r]);
    }
#pragma unroll
    for (int r = 0; r < 4; ++r) a2[r] += sx[g*4 + r][c];

    // LN per row (64 cols spread over 2 warps)
    float s1[4], s2[4];
#pragma unroll
    for (int r = 0; r < 4; ++r) { s1[r] = a2[r]; s2[r] = a2[r]*a2[r]; }
#pragma unroll
    for (int off = 16; off; off >>= 1) {
#pragma unroll
        for (int r = 0; r < 4; ++r) {
            s1[r] += __shfl_xor_sync(0xffffffffu, s1[r], off);
            s2[r] += __shfl_xor_sync(0xffffffffu, s2[r], off);
        }
    }
    int lane = tid & 31, half = (tid >> 5) & 1;
    if (lane == 0) {
#pragma unroll
        for (int r = 0; r < 4; ++r) {
            sred[g*4 + r][half][0] = s1[r];
            sred[g*4 + r][half][1] = s2[r];
        }
    }
    __syncthreads();
    float nsv = ns[iblk*64 + c], nbv = nb[iblk*64 + c];
#pragma unroll
    for (int r = 0; r < 4; ++r) {
        int rr = g*4 + r;
        float tot  = sred[rr][0][0] + sred[rr][1][0];
        float tot2 = sred[rr][0][1] + sred[rr][1][1];
        float mu = tot * (1.f/64.f);
        float var = tot2 * (1.f/64.f) - mu*mu;
        float rstd = rsqrtf(var + 1e-6f);
        float y = (a2[r] - mu) * rstd * nsv + nbv;
        sy[rr][c] = y;
        dst[(r0 + rr)*64 + c] = y;
    }
    __syncthreads();

    if (nblk < 0) return;

    // projections for next block from sy
    const float* Wm[3]; const float* Bm[3]; float* Dm[3]; int nmat;
    if (side == 0) {
        nmat = 1;
        Wm[0] = wq + nblk*4096; Bm[0] = bq + nblk*64; Dm[0] = g_q1;
    } else {
        nmat = 3;
        Wm[0] = wq + nblk*4096; Bm[0] = bq + nblk*64; Dm[0] = g_q2;
        Wm[1] = wk + nblk*4096; Bm[1] = bk + nblk*64; Dm[1] = g_kk;
        Wm[2] = wv + nblk*4096; Bm[2] = bv + nblk*64; Dm[2] = g_vv;
    }
    for (int mm = 0; mm < nmat; ++mm) {
        const float* W = Wm[mm];
        float bv = Bm[mm][c];
        float pa[4];
#pragma unroll
        for (int r = 0; r < 4; ++r) pa[r] = bv;
#pragma unroll 8
        for (int k = 0; k < 64; ++k) {
            float w = W[k*64 + c];
#pragma unroll
            for (int r = 0; r < 4; ++r) pa[r] = fmaf(sy[g*4 + r][k], w, pa[r]);
        }
#pragma unroll
        for (int r = 0; r < 4; ++r) Dm[mm][(r0 + g*4 + r)*64 + c] = pa[r];
    }
}

// ---------------------------------------------------------------------------
// Head: final LN + MLP 64->128 relu ->2.  out = [mu(2048) | std(2048)]
// ---------------------------------------------------------------------------
__global__ __launch_bounds__(128) void head_kernel(
    const float* __restrict__ fns, const float* __restrict__ fnb,
    const float* __restrict__ hw1, const float* __restrict__ hb1,
    const float* __restrict__ hw2, const float* __restrict__ hb2,
    float* __restrict__ out)
{
    __shared__ float sx[64], sh[128], sp0[128], sp1[128], sred[2];
    int row = blockIdx.x, tid = threadIdx.x;
    if (tid < 64) sx[tid] = g_qvs[row*64 + tid];
    __syncthreads();
    if (tid < 32) {
        float v0 = sx[tid], v1 = sx[tid + 32];
        float s = v0 + v1;
#pragma unroll
        for (int off = 16; off; off >>= 1)
            s += __shfl_xor_sync(0xffffffffu, s, off);
        float mu = s * (1.f/64.f);
        float e0 = v0 - mu, e1 = v1 - mu;
        float qv = fmaf(e0, e0, e1*e1);
#pragma unroll
        for (int off = 16; off; off >>= 1)
            qv += __shfl_xor_sync(0xffffffffu, qv, off);
        if (tid == 0) { sred[0] = mu; sred[1] = rsqrtf(qv*(1.f/64.f) + 1e-6f); }
    }
    __syncthreads();
    if (tid < 64) sx[tid] = (sx[tid] - sred[0]) * sred[1] * fns[tid] + fnb[tid];
    __syncthreads();
    float acc = hb1[tid];
#pragma unroll 16
    for (int k = 0; k < 64; ++k) acc = fmaf(sx[k], hw1[k*128 + tid], acc);
    sh[tid] = fmaxf(acc, 0.f);
    __syncthreads();
    sp0[tid] = sh[tid] * hw2[tid*2 + 0];
    sp1[tid] = sh[tid] * hw2[tid*2 + 1];
    __syncthreads();
    for (int s = 64; s > 0; s >>= 1) {
        if (tid < s) { sp0[tid] += sp0[tid + s]; sp1[tid] += sp1[tid + s]; }
        __syncthreads();
    }
    if (tid == 0) {
        out[row]        = sp0[0] + hb2[0];
        out[2048 + row] = __expf(0.5f * (sp1[0] + hb2[1]));
    }
}

// ---------------------------------------------------------------------------
extern "C" void kernel_launch(void* const* d_in, const int* in_sizes, int n_in,
                              void* d_out, int out_size)
{
    const float* s_ctx   = (const float*)d_in[0];
    const float* f_ctx   = (const float*)d_in[1];
    const float* s_test  = (const float*)d_in[2];
    const float* table   = (const float*)d_in[3];
    const float* emb_w1  = (const float*)d_in[4];
    const float* emb_b1  = (const float*)d_in[5];
    const float* emb_w2  = (const float*)d_in[6];
    const float* emb_b2  = (const float*)d_in[7];
    const float* attn_wq = (const float*)d_in[8];
    const float* attn_bq = (const float*)d_in[9];
    const float* attn_wk = (const float*)d_in[10];
    const float* attn_bk = (const float*)d_in[11];
    const float* attn_wv = (const float*)d_in[12];
    const float* attn_bv = (const float*)d_in[13];
    const float* attn_wo = (const float*)d_in[14];
    const float* attn_bo = (const float*)d_in[15];
    const float* ffn_w1  = (const float*)d_in[16];
    const float* ffn_b1  = (const float*)d_in[17];
    const float* ffn_w2  = (const float*)d_in[18];
    const float* ffn_b2  = (const float*)d_in[19];
    const float* bias_w1 = (const float*)d_in[20];
    const float* bias_b1 = (const float*)d_in[21];
    const float* bias_w2 = (const float*)d_in[22];
    const float* bias_b2 = (const float*)d_in[23];
    const float* norm_s  = (const float*)d_in[24];
    const float* norm_b  = (const float*)d_in[25];
    const float* fnorm_s = (const float*)d_in[26];
    const float* fnorm_b = (const float*)d_in[27];
    const float* head_w1 = (const float*)d_in[28];
    const float* head_b1 = (const float*)d_in[29];
    const float* head_w2 = (const float*)d_in[30];
    const float* head_b2 = (const float*)d_in[31];

    bias_setup_kernel<<<6, 32>>>(bias_w1, bias_b1, bias_w2, bias_b2);
    embed_kernel<<<4096, 256>>>(s_ctx, f_ctx, s_test, table,
                                emb_w1, emb_b1, emb_w2, emb_b2);
    proj_kernel<<<dim3(64, 4), 256>>>(0, attn_wq, attn_bq,
                                      attn_wk, attn_bk, attn_wv, attn_bv);
    for (int i = 0; i < 6; ++i) {
        attn_kernel<<<dim3(256, BB, 2), 256>>>(i, s_test, s_ctx,
                                               attn_wo, attn_bo, norm_s, norm_b);
        ffnproj_kernel<<<512, 128>>>(i, (i < 5) ? i + 1 : -1,
                                     ffn_w1, ffn_b1, ffn_w2, ffn_b2,
                                     norm_s, norm_b,
                                     attn_wq, attn_bq, attn_wk, attn_bk,
                                     attn_wv, attn_bv);
    }
    head_kernel<<<2048, 128>>>(fnorm_s, fnorm_b, head_w1, head_b1,
                               head_w2, head_b2, (float*)d_out);
}

// round 7
// speedup vs baseline: 3.1222x; 1.5378x over previous
#include <cuda_runtime.h>

#define BB 2
#define LL 1024
#define DD 64
#define NROWS (BB*LL)
#define SCALE 0.35355339059327373f
#define LOG2E 1.4426950408889634f
#define SCALE2 (SCALE * LOG2E)

// persistent activations (no allocation allowed)
__device__ float g_qvs[NROWS*DD];
__device__ float g_kvs[NROWS*DD];
__device__ float g_attq[NROWS*DD];
__device__ float g_attk[NROWS*DD];
__device__ float g_q1[NROWS*DD];
__device__ float g_q2[NROWS*DD];
__device__ float g_kk[NROWS*DD];
__device__ float g_vv[NROWS*DD];

// piecewise-linear distance-bias tables (per block), pre-scaled by log2(e)
__device__ float g_pl_t[6][16];       // sorted breakpoints
__device__ float g_pl_AC[6][17][16];  // per interval: A[8], C[8] (C includes b2)
__device__ int   g_pl_i0[6];          // #{t_i <= 0}: search starts here (16 => skip)

__device__ __forceinline__ float ex2f(float x) {
    float r; asm("ex2.approx.f32 %0, %1;" : "=f"(r) : "f"(x)); return r;
}

// ---------------------------------------------------------------------------
// Setup: fold dist-bias MLP (1->16 relu ->8) into 17-interval piecewise-linear
// form, pre-scaled by log2(e) so scores feed ex2 directly.
// ---------------------------------------------------------------------------
__global__ void bias_setup_kernel(
    const float* __restrict__ bw1, const float* __restrict__ bb1,
    const float* __restrict__ bw2, const float* __restrict__ bb2)
{
    int i = blockIdx.x;
    if (threadIdx.x != 0) return;
    float w1[16], b1[16], t[16];
    for (int j = 0; j < 16; ++j) {
        w1[j] = bw1[i*16 + j];
        b1[j] = bb1[i*16 + j];
        t[j]  = (w1[j] != 0.f) ? (-b1[j] / w1[j]) : -1e30f;
    }
    int ord[16];
    for (int j = 0; j < 16; ++j) ord[j] = j;
    for (int a = 1; a < 16; ++a) {          // insertion sort by t
        int o = ord[a]; float tv = t[o]; int b = a - 1;
        while (b >= 0 && t[ord[b]] > tv) { ord[b+1] = ord[b]; --b; }
        ord[b+1] = o;
    }
    int i0 = 0;
    for (int j = 0; j < 16; ++j) {
        g_pl_t[i][j] = t[ord[j]];
        if (t[ord[j]] <= 0.f) ++i0;
    }
    g_pl_i0[i] = i0;                        // dist >= 0 => first i0 always passed
    for (int m = 0; m <= 16; ++m) {
        float A[8], C[8];
        for (int h = 0; h < 8; ++h) { A[h] = 0.f; C[h] = 0.f; }
        for (int a = 0; a < 16; ++a) {
            int j = ord[a];
            bool act;
            if (w1[j] > 0.f)      act = (a < m);
            else if (w1[j] < 0.f) act = (a >= m);
            else                  act = (b1[j] > 0.f);
            if (act) {
                for (int h = 0; h < 8; ++h) {
                    A[h] += w1[j] * bw2[i*128 + j*8 + h];
                    C[h] += b1[j] * bw2[i*128 + j*8 + h];
                }
            }
        }
        for (int h = 0; h < 8; ++h) {
            g_pl_AC[i][m][h]     = A[h] * LOG2E;
            g_pl_AC[i][m][8 + h] = (C[h] + bb2[i*8 + h]) * LOG2E;
        }
    }
}

// ---------------------------------------------------------------------------
// Embed: row-wise MLP concat(obs,s,f)[7] -> 256 -> 64
// ---------------------------------------------------------------------------
__global__ __launch_bounds__(256) void embed_kernel(
    const float* __restrict__ s_ctx, const float* __restrict__ f_ctx,
    const float* __restrict__ s_test, const float* __restrict__ table,
    const float* __restrict__ w1, const float* __restrict__ b1,
    const float* __restrict__ w2, const float* __restrict__ b2)
{
    __shared__ float xs[8];
    __shared__ float h[256];
    __shared__ float part[256];
    int row = blockIdx.x, tid = threadIdx.x;
    int sideq = row >> 11;
    int r = row & 2047;
    int b = r >> 10, pos = r & 1023;
    if (tid < 7) {
        float v;
        if (sideq == 0) {
            v = (tid < 4) ? table[4 + tid]
              : (tid < 6) ? s_ctx[(b*LL + pos)*2 + tid - 4]
                          : f_ctx[b*LL + pos];
        } else {
            v = (tid < 4) ? table[tid]
              : (tid < 6) ? s_test[(b*LL + pos)*2 + tid - 4]
                          : 0.f;
        }
        xs[tid] = v;
    }
    __syncthreads();
    float acc = b1[tid];
#pragma unroll
    for (int i = 0; i < 7; ++i) acc = fmaf(xs[i], w1[i*256 + tid], acc);
    h[tid] = fmaxf(acc, 0.f);
    __syncthreads();
    int o = tid & 63, half = tid >> 6;
    float p = 0.f;
#pragma unroll 8
    for (int j = half*64; j < half*64 + 64; ++j) p = fmaf(h[j], w2[j*64 + o], p);
    part[tid] = p;
    __syncthreads();
    if (tid < 64) {
        float v = part[tid] + part[tid+64] + part[tid+128] + part[tid+192] + b2[tid];
        float* dst = sideq ? g_qvs : g_kvs;
        dst[(b*LL + pos)*64 + tid] = v;
    }
}

// ---------------------------------------------------------------------------
// Projections (block 0 only)
// ---------------------------------------------------------------------------
__global__ __launch_bounds__(256) void proj_kernel(
    int iblk,
    const float* __restrict__ wq, const float* __restrict__ bq,
    const float* __restrict__ wk, const float* __restrict__ bk,
    const float* __restrict__ wv, const float* __restrict__ bv)
{
    __shared__ float sW[64*64];
    __shared__ float sX[32*64];
    int tid = threadIdx.x;
    int mat = blockIdx.y;
    const float *X, *W, *bias; float* dst;
    if (mat == 0)      { X = g_qvs; W = wq + iblk*4096; bias = bq + iblk*64; dst = g_q1; }
    else if (mat == 1) { X = g_kvs; W = wq + iblk*4096; bias = bq + iblk*64; dst = g_q2; }
    else if (mat == 2) { X = g_kvs; W = wk + iblk*4096; bias = bk + iblk*64; dst = g_kk; }
    else               { X = g_kvs; W = wv + iblk*4096; bias = bv + iblk*64; dst = g_vv; }
    int row0 = blockIdx.x * 32;
    for (int n = tid; n < 4096; n += 256) sW[n] = W[n];
    for (int n = tid; n < 2048; n += 256) sX[n] = X[row0*64 + n];
    __syncthreads();
    int r = tid >> 3, c0 = (tid & 7) * 8;
    float acc[8];
#pragma unroll
    for (int i = 0; i < 8; ++i) acc[i] = bias[c0 + i];
#pragma unroll 16
    for (int k = 0; k < 64; ++k) {
        float a = sX[r*64 + k];
#pragma unroll
        for (int i = 0; i < 8; ++i) acc[i] = fmaf(a, sW[k*64 + c0 + i], acc[i]);
    }
#pragma unroll
    for (int i = 0; i < 8; ++i) dst[(row0 + r)*64 + c0 + i] = acc[i];
}

// ---------------------------------------------------------------------------
// Fused biased attention + out-proj + residual + LN.
// grid (256, B, 2). CTA = 8 warps = 4 queries. Each warp: 2 queries x 2 heads
// (p = wid>>2 selects query pair, hq = wid&3 selects head pair) — every K/V
// LDS.128 feeds 4x FMAs (2 queries x 2 keys). PL bias with search skipped
// when all breakpoints <= 0 (true for this model: bias_b1 == 0). exp via ex2
// with log2e pre-folded into Q scale and A/C tables.
// ---------------------------------------------------------------------------
__global__ __launch_bounds__(256, 2) void attn_kernel(
    int iblk,
    const float* __restrict__ s_test, const float* __restrict__ s_ctx,
    const float* __restrict__ wo, const float* __restrict__ bo,
    const float* __restrict__ ns, const float* __restrict__ nb)
{
    __shared__ float4 sKf4[1024];   // 64 keys x 16 float4, XOR swizzled
    __shared__ float4 sVf4[1024];
    __shared__ float  sQ[256];      // 4 queries x 64, pre-scaled by SCALE*log2e
    __shared__ float2 sSk[64];
    __shared__ float2 sAC2[136];    // 17 intervals x 16 floats
    __shared__ float  sO[256];
    __shared__ float  sRed[4][2][2];

    const int tid = threadIdx.x, wid = tid >> 5, lane = tid & 31;
    const int side = blockIdx.z, b = blockIdx.y;
    const int p  = wid >> 2;        // query pair (queries 2p, 2p+1 of the CTA)
    const int hq = wid & 3;         // head pair (global heads 2hq, 2hq+1)
    const int qrow0 = b*LL + blockIdx.x*4 + 2*p;
    const int qrow1 = qrow0 + 1;

    const float* Qp  = side ? g_q2 : g_q1;
    const float* sqc = side ? s_ctx : s_test;

    for (int n = tid; n < 272; n += 256)
        ((float*)sAC2)[n] = ((const float*)g_pl_AC)[iblk*272 + n];
    sQ[tid] = Qp[(b*LL + blockIdx.x*4)*64 + tid] * SCALE2;

    const int i0 = g_pl_i0[iblk];
    const float* trg = g_pl_t[iblk];
    const float q0x = sqc[qrow0*2], q0y = sqc[qrow0*2 + 1];
    const float q1x = sqc[qrow1*2], q1y = sqc[qrow1*2 + 1];

    float l[4] = {0.f, 0.f, 0.f, 0.f};   // [q*2+h]
    float o[32];                          // [q*16 + h*8 + d]
#pragma unroll
    for (int d = 0; d < 32; ++d) o[d] = 0.f;

    const int ksw = lane & 15, kb0 = lane << 4;
    int ikk[4];
#pragma unroll
    for (int cc = 0; cc < 4; ++cc) ikk[cc] = kb0 + ((4*hq + cc) ^ ksw);
    const float4* sQw = ((const float4*)sQ) + p*32 + 4*hq;
    const float4* Kg = (const float4*)(g_kk + b*LL*64);
    const float4* Vg = (const float4*)(g_vv + b*LL*64);
    const float2* Skg = (const float2*)s_ctx + b*LL;

    for (int t = 0; t < 16; ++t) {
        __syncthreads();
#pragma unroll
        for (int n4 = 0; n4 < 4; ++n4) {
            int n = n4*256 + tid;
            int kr = n >> 4, c = n & 15;
            int sw = (kr << 4) + (c ^ (kr & 15));
            sKf4[sw] = Kg[t*1024 + n];
            sVf4[sw] = Vg[t*1024 + n];
        }
        if (tid < 64) sSk[tid] = Skg[t*64 + tid];
        __syncthreads();

        // 4 distances: 2 queries x 2 keys (keys lane, lane+32)
        float2 ck0 = sSk[lane], ck1 = sSk[lane + 32];
        float dx, dy;
        dx = q0x - ck0.x; dy = q0y - ck0.y; float d00 = fmaf(dx, dx, dy*dy);
        dx = q0x - ck1.x; dy = q0y - ck1.y; float d01 = fmaf(dx, dx, dy*dy);
        dx = q1x - ck0.x; dy = q1y - ck0.y; float d10 = fmaf(dx, dx, dy*dy);
        dx = q1x - ck1.x; dy = q1y - ck1.y; float d11 = fmaf(dx, dx, dy*dy);

        // interval index (loop empty when i0 == 16 — the real-data case)
        int m00 = i0, m01 = i0, m10 = i0, m11 = i0;
        for (int i = i0; i < 16; ++i) {
            float tv = trg[i];
            m00 += d00 > tv; m01 += d01 > tv;
            m10 += d10 > tv; m11 += d11 > tv;
        }

        float2 Aa = sAC2[m00*8 + hq], Ca = sAC2[m00*8 + 4 + hq];
        float2 Ab = sAC2[m01*8 + hq], Cb = sAC2[m01*8 + 4 + hq];
        float2 Ac = sAC2[m10*8 + hq], Cc = sAC2[m10*8 + 4 + hq];
        float2 Ad = sAC2[m11*8 + hq], Cd = sAC2[m11*8 + 4 + hq];

        // s[q*4 + k*2 + h]
        float s[8];
        s[0] = fmaf(Aa.x, d00, Ca.x);  s[1] = fmaf(Aa.y, d00, Ca.y);
        s[2] = fmaf(Ab.x, d01, Cb.x);  s[3] = fmaf(Ab.y, d01, Cb.y);
        s[4] = fmaf(Ac.x, d10, Cc.x);  s[5] = fmaf(Ac.y, d10, Cc.y);
        s[6] = fmaf(Ad.x, d11, Cd.x);  s[7] = fmaf(Ad.y, d11, Cd.y);

        // QK dots: each K load feeds both queries
#pragma unroll
        for (int cc = 0; cc < 4; ++cc) {
            const int h = cc >> 1;
            float4 k0 = sKf4[ikk[cc]];
            float4 k1 = sKf4[ikk[cc] + 512];
            float4 qa = sQw[cc];
            float4 qb = sQw[16 + cc];
            s[h]   = fmaf(qa.x,k0.x,s[h]);   s[h]   = fmaf(qa.y,k0.y,s[h]);
            s[h]   = fmaf(qa.z,k0.z,s[h]);   s[h]   = fmaf(qa.w,k0.w,s[h]);
            s[2+h] = fmaf(qa.x,k1.x,s[2+h]); s[2+h] = fmaf(qa.y,k1.y,s[2+h]);
            s[2+h] = fmaf(qa.z,k1.z,s[2+h]); s[2+h] = fmaf(qa.w,k1.w,s[2+h]);
            s[4+h] = fmaf(qb.x,k0.x,s[4+h]); s[4+h] = fmaf(qb.y,k0.y,s[4+h]);
            s[4+h] = fmaf(qb.z,k0.z,s[4+h]); s[4+h] = fmaf(qb.w,k0.w,s[4+h]);
            s[6+h] = fmaf(qb.x,k1.x,s[6+h]); s[6+h] = fmaf(qb.y,k1.y,s[6+h]);
            s[6+h] = fmaf(qb.z,k1.z,s[6+h]); s[6+h] = fmaf(qb.w,k1.w,s[6+h]);
        }

        float pr[8];
#pragma unroll
        for (int i = 0; i < 8; ++i) pr[i] = ex2f(s[i]);
        l[0] += pr[0] + pr[2];
        l[1] += pr[1] + pr[3];
        l[2] += pr[4] + pr[6];
        l[3] += pr[5] + pr[7];

        // V accumulation: each V load feeds both queries
#pragma unroll
        for (int cc = 0; cc < 4; ++cc) {
            const int h = cc >> 1, d0 = (cc & 1) * 4;
            float4 v0 = sVf4[ikk[cc]];
            float4 v1 = sVf4[ikk[cc] + 512];
            o[h*8+d0+0] = fmaf(pr[h],   v0.x, o[h*8+d0+0]);
            o[h*8+d0+0] = fmaf(pr[2+h], v1.x, o[h*8+d0+0]);
            o[h*8+d0+1] = fmaf(pr[h],   v0.y, o[h*8+d0+1]);
            o[h*8+d0+1] = fmaf(pr[2+h], v1.y, o[h*8+d0+1]);
            o[h*8+d0+2] = fmaf(pr[h],   v0.z, o[h*8+d0+2]);
            o[h*8+d0+2] = fmaf(pr[2+h], v1.z, o[h*8+d0+2]);
            o[h*8+d0+3] = fmaf(pr[h],   v0.w, o[h*8+d0+3]);
            o[h*8+d0+3] = fmaf(pr[2+h], v1.w, o[h*8+d0+3]);
            o[16+h*8+d0+0] = fmaf(pr[4+h], v0.x, o[16+h*8+d0+0]);
            o[16+h*8+d0+0] = fmaf(pr[6+h], v1.x, o[16+h*8+d0+0]);
            o[16+h*8+d0+1] = fmaf(pr[4+h], v0.y, o[16+h*8+d0+1]);
            o[16+h*8+d0+1] = fmaf(pr[6+h], v1.y, o[16+h*8+d0+1]);
            o[16+h*8+d0+2] = fmaf(pr[4+h], v0.z, o[16+h*8+d0+2]);
            o[16+h*8+d0+2] = fmaf(pr[6+h], v1.z, o[16+h*8+d0+2]);
            o[16+h*8+d0+3] = fmaf(pr[4+h], v0.w, o[16+h*8+d0+3]);
            o[16+h*8+d0+3] = fmaf(pr[6+h], v1.w, o[16+h*8+d0+3]);
        }
    }

    // merge lanes (butterfly)
#pragma unroll
    for (int i = 0; i < 4; ++i) {
        float lh = l[i];
#pragma unroll
        for (int off = 16; off; off >>= 1)
            lh += __shfl_xor_sync(0xffffffffu, lh, off);
        l[i] = lh;
    }
#pragma unroll
    for (int d = 0; d < 32; ++d) {
        float v = o[d];
#pragma unroll
        for (int off = 16; off; off >>= 1)
            v += __shfl_xor_sync(0xffffffffu, v, off);
        o[d] = v;
    }
    float inv[4];
#pragma unroll
    for (int i = 0; i < 4; ++i) inv[i] = 1.f / l[i];
#pragma unroll
    for (int d = 0; d < 32; ++d) o[d] *= inv[(d >> 4)*2 + ((d >> 3) & 1)];

    // lane extraction: lane holds o[lane]
    float myv = 0.f;
#pragma unroll
    for (int i = 0; i < 32; ++i)
        if (lane == i) myv = o[i];

    __syncthreads();   // all warps done with sK/sV
    sO[(2*p + (lane >> 4))*64 + 16*hq + (lane & 15)] = myv;
    float* sWo = (float*)sKf4;
    const float* Wog = wo + iblk*4096;
    for (int n = tid; n < 4096; n += 256) sWo[n] = Wog[n];
    __syncthreads();

    // out-proj + residual + LN: thread (qc = tid>>6, c = tid&63)
    const int qc = tid >> 6, c = tid & 63;
    const int qrow_e = b*LL + blockIdx.x*4 + qc;
    float acc = bo[iblk*64 + c];
#pragma unroll 16
    for (int i = 0; i < 64; ++i)
        acc = fmaf(sO[qc*64 + i], sWo[i*64 + c], acc);
    const float* src = side ? g_kvs : g_qvs;
    acc += src[qrow_e*64 + c];

    float s1 = acc, s2 = acc*acc;
#pragma unroll
    for (int off = 16; off; off >>= 1) {
        s1 += __shfl_xor_sync(0xffffffffu, s1, off);
        s2 += __shfl_xor_sync(0xffffffffu, s2, off);
    }
    const int half = (tid >> 5) & 1;
    if (lane == 0) { sRed[qc][half][0] = s1; sRed[qc][half][1] = s2; }
    __syncthreads();
    float tot  = sRed[qc][0][0] + sRed[qc][1][0];
    float tot2 = sRed[qc][0][1] + sRed[qc][1][1];
    float mu = tot * (1.f/64.f);
    float var = tot2 * (1.f/64.f) - mu*mu;
    float rstd = rsqrtf(var + 1e-6f);

    float* outp = side ? g_attk : g_attq;
    outp[qrow_e*64 + c] = (acc - mu) * rstd * ns[iblk*64 + c] + nb[iblk*64 + c];
}

// ---------------------------------------------------------------------------
// FFN (64->128 relu ->64) + residual + LN + NEXT-BLOCK projections.
// ---------------------------------------------------------------------------
__global__ __launch_bounds__(128) void ffnproj_kernel(
    int iblk, int nblk,
    const float* __restrict__ fw1, const float* __restrict__ fb1,
    const float* __restrict__ fw2, const float* __restrict__ fb2,
    const float* __restrict__ ns, const float* __restrict__ nb,
    const float* __restrict__ wq, const float* __restrict__ bq,
    const float* __restrict__ wk, const float* __restrict__ bk,
    const float* __restrict__ wv, const float* __restrict__ bv)
{
    __shared__ float sx[8][64];
    __shared__ float sh[8][128];
    __shared__ float sy[8][64];
    __shared__ float sred[8][2][2];

    int tid = threadIdx.x;
    int row0 = blockIdx.x * 8;
    int side = row0 >> 11;
    int r0 = row0 & 2047;
    const float* src = side ? g_attk : g_attq;
    float* dst = side ? g_kvs : g_qvs;

    for (int n = tid; n < 512; n += 128) sx[n >> 6][n & 63] = src[r0*64 + n];
    __syncthreads();

    const float* W1 = fw1 + iblk*8192;
    float b1v = fb1[iblk*128 + tid];
    float acc[8];
#pragma unroll
    for (int r = 0; r < 8; ++r) acc[r] = b1v;
#pragma unroll 8
    for (int k = 0; k < 64; ++k) {
        float w = W1[k*128 + tid];
#pragma unroll
        for (int r = 0; r < 8; ++r) acc[r] = fmaf(sx[r][k], w, acc[r]);
    }
#pragma unroll
    for (int r = 0; r < 8; ++r) sh[r][tid] = fmaxf(acc[r], 0.f);
    __syncthreads();

    const float* W2 = fw2 + iblk*8192;
    int c = tid & 63, g = tid >> 6;
    float b2v = fb2[iblk*64 + c];
    float a2[4];
#pragma unroll
    for (int r = 0; r < 4; ++r) a2[r] = b2v;
#pragma unroll 8
    for (int k = 0; k < 128; ++k) {
        float w = W2[k*64 + c];
#pragma unroll
        for (int r = 0; r < 4; ++r) a2[r] = fmaf(sh[g*4 + r][k], w, a2[r]);
    }
#pragma unroll
    for (int r = 0; r < 4; ++r) a2[r] += sx[g*4 + r][c];

    float s1[4], s2[4];
#pragma unroll
    for (int r = 0; r < 4; ++r) { s1[r] = a2[r]; s2[r] = a2[r]*a2[r]; }
#pragma unroll
    for (int off = 16; off; off >>= 1) {
#pragma unroll
        for (int r = 0; r < 4; ++r) {
            s1[r] += __shfl_xor_sync(0xffffffffu, s1[r], off);
            s2[r] += __shfl_xor_sync(0xffffffffu, s2[r], off);
        }
    }
    int lane = tid & 31, half = (tid >> 5) & 1;
    if (lane == 0) {
#pragma unroll
        for (int r = 0; r < 4; ++r) {
            sred[g*4 + r][half][0] = s1[r];
            sred[g*4 + r][half][1] = s2[r];
        }
    }
    __syncthreads();
    float nsv = ns[iblk*64 + c], nbv = nb[iblk*64 + c];
#pragma unroll
    for (int r = 0; r < 4; ++r) {
        int rr = g*4 + r;
        float tot  = sred[rr][0][0] + sred[rr][1][0];
        float tot2 = sred[rr][0][1] + sred[rr][1][1];
        float mu = tot * (1.f/64.f);
        float var = tot2 * (1.f/64.f) - mu*mu;
        float rstd = rsqrtf(var + 1e-6f);
        float y = (a2[r] - mu) * rstd * nsv + nbv;
        sy[rr][c] = y;
        dst[(r0 + rr)*64 + c] = y;
    }
    __syncthreads();

    if (nblk < 0) return;

    const float* Wm[3]; const float* Bm[3]; float* Dm[3]; int nmat;
    if (side == 0) {
        nmat = 1;
        Wm[0] = wq + nblk*4096; Bm[0] = bq + nblk*64; Dm[0] = g_q1;
    } else {
        nmat = 3;
        Wm[0] = wq + nblk*4096; Bm[0] = bq + nblk*64; Dm[0] = g_q2;
        Wm[1] = wk + nblk*4096; Bm[1] = bk + nblk*64; Dm[1] = g_kk;
        Wm[2] = wv + nblk*4096; Bm[2] = bv + nblk*64; Dm[2] = g_vv;
    }
    for (int mm = 0; mm < nmat; ++mm) {
        const float* W = Wm[mm];
        float bv = Bm[mm][c];
        float pa[4];
#pragma unroll
        for (int r = 0; r < 4; ++r) pa[r] = bv;
#pragma unroll 8
        for (int k = 0; k < 64; ++k) {
            float w = W[k*64 + c];
#pragma unroll
            for (int r = 0; r < 4; ++r) pa[r] = fmaf(sy[g*4 + r][k], w, pa[r]);
        }
#pragma unroll
        for (int r = 0; r < 4; ++r) Dm[mm][(r0 + g*4 + r)*64 + c] = pa[r];
    }
}

// ---------------------------------------------------------------------------
// Head: final LN + MLP 64->128 relu ->2.  out = [mu(2048) | std(2048)]
// ---------------------------------------------------------------------------
__global__ __launch_bounds__(128) void head_kernel(
    const float* __restrict__ fns, const float* __restrict__ fnb,
    const float* __restrict__ hw1, const float* __restrict__ hb1,
    const float* __restrict__ hw2, const float* __restrict__ hb2,
    float* __restrict__ out)
{
    __shared__ float sx[64], sh[128], sp0[128], sp1[128], sred[2];
    int row = blockIdx.x, tid = threadIdx.x;
    if (tid < 64) sx[tid] = g_qvs[row*64 + tid];
    __syncthreads();
    if (tid < 32) {
        float v0 = sx[tid], v1 = sx[tid + 32];
        float s = v0 + v1;
#pragma unroll
        for (int off = 16; off; off >>= 1)
            s += __shfl_xor_sync(0xffffffffu, s, off);
        float mu = s * (1.f/64.f);
        float e0 = v0 - mu, e1 = v1 - mu;
        float qv = fmaf(e0, e0, e1*e1);
#pragma unroll
        for (int off = 16; off; off >>= 1)
            qv += __shfl_xor_sync(0xffffffffu, qv, off);
        if (tid == 0) { sred[0] = mu; sred[1] = rsqrtf(qv*(1.f/64.f) + 1e-6f); }
    }
    __syncthreads();
    if (tid < 64) sx[tid] = (sx[tid] - sred[0]) * sred[1] * fns[tid] + fnb[tid];
    __syncthreads();
    float acc = hb1[tid];
#pragma unroll 16
    for (int k = 0; k < 64; ++k) acc = fmaf(sx[k], hw1[k*128 + tid], acc);
    sh[tid] = fmaxf(acc, 0.f);
    __syncthreads();
    sp0[tid] = sh[tid] * hw2[tid*2 + 0];
    sp1[tid] = sh[tid] * hw2[tid*2 + 1];
    __syncthreads();
    for (int s = 64; s > 0; s >>= 1) {
        if (tid < s) { sp0[tid] += sp0[tid + s]; sp1[tid] += sp1[tid + s]; }
        __syncthreads();
    }
    if (tid == 0) {
        out[row]        = sp0[0] + hb2[0];
        out[2048 + row] = __expf(0.5f * (sp1[0] + hb2[1]));
    }
}

// ---------------------------------------------------------------------------
extern "C" void kernel_launch(void* const* d_in, const int* in_sizes, int n_in,
                              void* d_out, int out_size)
{
    const float* s_ctx   = (const float*)d_in[0];
    const float* f_ctx   = (const float*)d_in[1];
    const float* s_test  = (const float*)d_in[2];
    const float* table   = (const float*)d_in[3];
    const float* emb_w1  = (const float*)d_in[4];
    const float* emb_b1  = (const float*)d_in[5];
    const float* emb_w2  = (const float*)d_in[6];
    const float* emb_b2  = (const float*)d_in[7];
    const float* attn_wq = (const float*)d_in[8];
    const float* attn_bq = (const float*)d_in[9];
    const float* attn_wk = (const float*)d_in[10];
    const float* attn_bk = (const float*)d_in[11];
    const float* attn_wv = (const float*)d_in[12];
    const float* attn_bv = (const float*)d_in[13];
    const float* attn_wo = (const float*)d_in[14];
    const float* attn_bo = (const float*)d_in[15];
    const float* ffn_w1  = (const float*)d_in[16];
    const float* ffn_b1  = (const float*)d_in[17];
    const float* ffn_w2  = (const float*)d_in[18];
    const float* ffn_b2  = (const float*)d_in[19];
    const float* bias_w1 = (const float*)d_in[20];
    const float* bias_b1 = (const float*)d_in[21];
    const float* bias_w2 = (const float*)d_in[22];
    const float* bias_b2 = (const float*)d_in[23];
    const float* norm_s  = (const float*)d_in[24];
    const float* norm_b  = (const float*)d_in[25];
    const float* fnorm_s = (const float*)d_in[26];
    const float* fnorm_b = (const float*)d_in[27];
    const float* head_w1 = (const float*)d_in[28];
    const float* head_b1 = (const float*)d_in[29];
    const float* head_w2 = (const float*)d_in[30];
    const float* head_b2 = (const float*)d_in[31];

    bias_setup_kernel<<<6, 32>>>(bias_w1, bias_b1, bias_w2, bias_b2);
    embed_kernel<<<4096, 256>>>(s_ctx, f_ctx, s_test, table,
                                emb_w1, emb_b1, emb_w2, emb_b2);
    proj_kernel<<<dim3(64, 4), 256>>>(0, attn_wq, attn_bq,
                                      attn_wk, attn_bk, attn_wv, attn_bv);
    for (int i = 0; i < 6; ++i) {
        attn_kernel<<<dim3(256, BB, 2), 256>>>(i, s_test, s_ctx,
                                               attn_wo, attn_bo, norm_s, norm_b);
        ffnproj_kernel<<<512, 128>>>(i, (i < 5) ? i + 1 : -1,
                                     ffn_w1, ffn_b1, ffn_w2, ffn_b2,
                                     norm_s, norm_b,
                                     attn_wq, attn_bq, attn_wk, attn_bk,
                                     attn_wv, attn_bv);
    }
    head_kernel<<<2048, 128>>>(fnorm_s, fnorm_b, head_w1, head_b1,
                               head_w2, head_b2, (float*)d_out);
}